// round 1
// baseline (speedup 1.0000x reference)
#include <cuda_runtime.h>
#include <cuda_bf16.h>
#include <cstddef>

// Problem constants
#define BB  4
#define SS  2048
#define DD  1024
#define HH  16
#define HDD 64
#define MTOK (BB*SS)          // 8192 token rows

// Scratch (device globals; no allocations allowed)
__device__ float g_qkv[(size_t)MTOK * 3 * DD];   // [8192, 3072]
__device__ float g_y  [(size_t)MTOK * DD];       // [8192, 1024]

// ---------------------------------------------------------------------------
// Tiled SGEMM: C[M,N] = A[M,K] @ B[K,N] + bias[N]
// BM=BN=128, BK=16, 256 threads, 8x8 micro-tile per thread.
// ---------------------------------------------------------------------------
__global__ __launch_bounds__(256)
void sgemm_bias_kernel(const float* __restrict__ A,
                       const float* __restrict__ B,
                       const float* __restrict__ bias,
                       float* __restrict__ C,
                       int M, int N, int K)
{
    const int BM = 128, BN = 128, BK = 16;
    __shared__ float As[BK][BM];   // A tile, transposed: As[k][m]
    __shared__ float Bs[BK][BN];   // B tile: Bs[k][n]

    const int tid = threadIdx.x;
    const int block_row = blockIdx.y * BM;
    const int block_col = blockIdx.x * BN;

    const int tx = tid & 15;   // 0..15 -> 8 output cols each
    const int ty = tid >> 4;   // 0..15 -> 8 output rows each

    // A tile load mapping: 128 rows x 16 cols = 512 float4 (along K); 2 per thread
    const int a_row  = tid >> 2;          // 0..63 (and +64)
    const int a_col4 = (tid & 3) << 2;    // 0,4,8,12
    // B tile load mapping: 16 rows x 128 cols = 512 float4 (along N); 2 per thread
    const int b_row = tid >> 5;           // 0..7 (and +8)
    const int b_col = (tid & 31) << 2;    // 0..124

    float acc[8][8];
    #pragma unroll
    for (int i = 0; i < 8; i++)
        #pragma unroll
        for (int j = 0; j < 8; j++) acc[i][j] = 0.f;

    for (int k0 = 0; k0 < K; k0 += BK) {
        #pragma unroll
        for (int i = 0; i < 2; i++) {
            int r = a_row + i * 64;
            float4 v = *reinterpret_cast<const float4*>(
                &A[(size_t)(block_row + r) * K + k0 + a_col4]);
            As[a_col4 + 0][r] = v.x;
            As[a_col4 + 1][r] = v.y;
            As[a_col4 + 2][r] = v.z;
            As[a_col4 + 3][r] = v.w;
        }
        #pragma unroll
        for (int i = 0; i < 2; i++) {
            int r = b_row + i * 8;
            *reinterpret_cast<float4*>(&Bs[r][b_col]) =
                *reinterpret_cast<const float4*>(
                    &B[(size_t)(k0 + r) * N + block_col + b_col]);
        }
        __syncthreads();

        #pragma unroll
        for (int kk = 0; kk < BK; kk++) {
            float af[8], bf[8];
            // vectorized shared loads (conflict-free / broadcast)
            float4 a0 = *reinterpret_cast<const float4*>(&As[kk][ty * 8 + 0]);
            float4 a1 = *reinterpret_cast<const float4*>(&As[kk][ty * 8 + 4]);
            float4 b0 = *reinterpret_cast<const float4*>(&Bs[kk][tx * 8 + 0]);
            float4 b1 = *reinterpret_cast<const float4*>(&Bs[kk][tx * 8 + 4]);
            af[0]=a0.x; af[1]=a0.y; af[2]=a0.z; af[3]=a0.w;
            af[4]=a1.x; af[5]=a1.y; af[6]=a1.z; af[7]=a1.w;
            bf[0]=b0.x; bf[1]=b0.y; bf[2]=b0.z; bf[3]=b0.w;
            bf[4]=b1.x; bf[5]=b1.y; bf[6]=b1.z; bf[7]=b1.w;
            #pragma unroll
            for (int i = 0; i < 8; i++)
                #pragma unroll
                for (int j = 0; j < 8; j++)
                    acc[i][j] = fmaf(af[i], bf[j], acc[i][j]);
        }
        __syncthreads();
    }

    #pragma unroll
    for (int i = 0; i < 8; i++) {
        int r = block_row + ty * 8 + i;
        #pragma unroll
        for (int j = 0; j < 8; j += 4) {
            int c = block_col + tx * 8 + j;
            float4 v;
            v.x = acc[i][j + 0] + bias[c + 0];
            v.y = acc[i][j + 1] + bias[c + 1];
            v.z = acc[i][j + 2] + bias[c + 2];
            v.w = acc[i][j + 3] + bias[c + 3];
            *reinterpret_cast<float4*>(&C[(size_t)r * N + c]) = v;
        }
    }
}

// ---------------------------------------------------------------------------
// Causal flash attention, fp32, one thread per query row.
// BM=128 query rows per CTA, BN=64 keys per tile. HD=64.
// Reads q/k/v directly out of the packed qkv buffer [8192, 3072].
// Writes y in [B,S,H,HD] (== [8192,1024]) layout, ready for the proj GEMM.
// ---------------------------------------------------------------------------
__global__ __launch_bounds__(128)
void flash_attn_kernel(const float* __restrict__ qkv, float* __restrict__ y)
{
    const int BM = 128, BN = 64;
    __shared__ float ksh[BN][HDD];   // 16 KB
    __shared__ float vsh[BN][HDD];   // 16 KB

    const int t = threadIdx.x;
    // reverse q-tile order: long (late) tiles scheduled first -> better wave balance
    const int qtile = (gridDim.x - 1) - blockIdx.x;
    const int h = blockIdx.y;
    const int b = blockIdx.z;
    const int qi = qtile * BM + t;            // global query index within sequence

    const float* qrow = qkv + ((size_t)(b * SS + qi)) * (3 * DD) + h * HDD;

    float q[HDD], acc[HDD];
    #pragma unroll
    for (int d = 0; d < HDD; d += 4) {
        float4 v = *reinterpret_cast<const float4*>(qrow + d);
        q[d + 0] = v.x * 0.125f;   // pre-scale by HD^-0.5
        q[d + 1] = v.y * 0.125f;
        q[d + 2] = v.z * 0.125f;
        q[d + 3] = v.w * 0.125f;
    }
    #pragma unroll
    for (int d = 0; d < HDD; d++) acc[d] = 0.f;

    float m = -1e30f, l = 0.f;

    const int kv_end = qtile * BM + BM;       // last key any thread in block needs (excl)
    for (int kv0 = 0; kv0 < kv_end; kv0 += BN) {
        // cooperative K/V tile load: 64 rows x 16 float4 = 1024 float4, 8 per thread
        #pragma unroll
        for (int i = 0; i < 8; i++) {
            int idx = t + i * 128;            // 0..1023
            int r   = idx >> 4;               // key row in tile
            int c4  = (idx & 15) << 2;        // col (float index)
            const float* kp = qkv + ((size_t)(b * SS + kv0 + r)) * (3 * DD)
                              + DD + h * HDD + c4;
            *reinterpret_cast<float4*>(&ksh[r][c4]) =
                *reinterpret_cast<const float4*>(kp);
            *reinterpret_cast<float4*>(&vsh[r][c4]) =
                *reinterpret_cast<const float4*>(kp + DD);   // V is D floats after K
        }
        __syncthreads();

        int jmax = qi - kv0 + 1;              // causal: keys <= qi
        if (jmax > BN) jmax = BN;

        for (int j = 0; j < jmax; j++) {
            // dot(q, k_j) with 4 independent accumulation chains
            float s0 = 0.f, s1 = 0.f, s2 = 0.f, s3 = 0.f;
            #pragma unroll
            for (int d = 0; d < HDD; d += 4) {
                float4 kv4 = *reinterpret_cast<const float4*>(&ksh[j][d]);
                s0 = fmaf(q[d + 0], kv4.x, s0);
                s1 = fmaf(q[d + 1], kv4.y, s1);
                s2 = fmaf(q[d + 2], kv4.z, s2);
                s3 = fmaf(q[d + 3], kv4.w, s3);
            }
            float s = (s0 + s1) + (s2 + s3);

            if (s > m) {                      // rare after warmup
                float corr = __expf(m - s);
                l *= corr;
                #pragma unroll
                for (int d = 0; d < HDD; d++) acc[d] *= corr;
                m = s;
            }
            float p = __expf(s - m);
            l += p;
            #pragma unroll
            for (int d = 0; d < HDD; d += 4) {
                float4 vv = *reinterpret_cast<const float4*>(&vsh[j][d]);
                acc[d + 0] = fmaf(p, vv.x, acc[d + 0]);
                acc[d + 1] = fmaf(p, vv.y, acc[d + 1]);
                acc[d + 2] = fmaf(p, vv.z, acc[d + 2]);
                acc[d + 3] = fmaf(p, vv.w, acc[d + 3]);
            }
        }
        __syncthreads();
    }

    float inv = 1.f / l;
    float* yrow = y + ((size_t)(b * SS + qi)) * DD + h * HDD;
    #pragma unroll
    for (int d = 0; d < HDD; d += 4) {
        float4 v;
        v.x = acc[d + 0] * inv;
        v.y = acc[d + 1] * inv;
        v.z = acc[d + 2] * inv;
        v.w = acc[d + 3] * inv;
        *reinterpret_cast<float4*>(yrow + d) = v;
    }
}

// ---------------------------------------------------------------------------
// Launch
// ---------------------------------------------------------------------------
extern "C" void kernel_launch(void* const* d_in, const int* in_sizes, int n_in,
                              void* d_out, int out_size)
{
    const float* x      = (const float*)d_in[0];  // [4,2048,1024]
    const float* W_attn = (const float*)d_in[1];  // [1024,3072]
    const float* b_attn = (const float*)d_in[2];  // [3072]
    const float* W_proj = (const float*)d_in[3];  // [1024,1024]
    const float* b_proj = (const float*)d_in[4];  // [1024]
    float* out = (float*)d_out;                   // [4,2048,1024]

    static float* qkv_ptr = nullptr;
    static float* y_ptr   = nullptr;
    if (!qkv_ptr) {   // first (non-captured) correctness call resolves symbols
        cudaGetSymbolAddress((void**)&qkv_ptr, g_qkv);
        cudaGetSymbolAddress((void**)&y_ptr,   g_y);
    }

    // 1) QKV GEMM: [8192,1024] @ [1024,3072] + b -> g_qkv
    {
        dim3 grid(3 * DD / 128, MTOK / 128);
        sgemm_bias_kernel<<<grid, 256>>>(x, W_attn, b_attn, qkv_ptr,
                                         MTOK, 3 * DD, DD);
    }

    // 2) causal flash attention -> g_y  (already in [B,S,D] layout)
    {
        dim3 grid(SS / 128, HH, BB);
        flash_attn_kernel<<<grid, 128>>>(qkv_ptr, y_ptr);
    }

    // 3) output projection: [8192,1024] @ [1024,1024] + b -> out
    {
        dim3 grid(DD / 128, MTOK / 128);
        sgemm_bias_kernel<<<grid, 256>>>(y_ptr, W_proj, b_proj, out,
                                         MTOK, DD, DD);
    }
}

// round 3
// speedup vs baseline: 1.4922x; 1.4922x over previous
#include <cuda_runtime.h>
#include <cuda_bf16.h>
#include <cstdint>
#include <cstddef>

// Problem constants
#define BB  4
#define SS  2048
#define DD  1024
#define HH  16
#define HDD 64
#define MTOK (BB*SS)          // 8192 token rows

// Scratch (device globals; no allocations allowed)
__device__ __align__(128) float g_qkv[(size_t)MTOK * 3 * DD];        // [8192, 3072]
__device__ __align__(128) float g_y  [(size_t)MTOK * DD];            // [8192, 1024]
__device__ __align__(128) __nv_bfloat16 g_wt_hi [(size_t)3 * DD * DD];  // W_attn^T hi [3072,1024]
__device__ __align__(128) __nv_bfloat16 g_wt_lo [(size_t)3 * DD * DD];  // W_attn^T lo
__device__ __align__(128) __nv_bfloat16 g_wpt_hi[(size_t)DD * DD];      // W_proj^T hi [1024,1024]
__device__ __align__(128) __nv_bfloat16 g_wpt_lo[(size_t)DD * DD];      // W_proj^T lo

// ---------------------------------------------------------------------------
// Warp-MMA helpers (sm_80+ path: ldmatrix + mma.sync — compiles on compute_103)
// ---------------------------------------------------------------------------
__device__ __forceinline__ uint32_t smem_u32(const void* p) {
    uint32_t a;
    asm("{ .reg .u64 t; cvta.to.shared.u64 t, %1; cvt.u32.u64 %0, t; }"
        : "=r"(a) : "l"(p));
    return a;
}
__device__ __forceinline__ void ldsm_x4(uint32_t* r, uint32_t addr) {
    asm volatile("ldmatrix.sync.aligned.m8n8.x4.shared.b16 {%0,%1,%2,%3}, [%4];"
                 : "=r"(r[0]), "=r"(r[1]), "=r"(r[2]), "=r"(r[3]) : "r"(addr));
}
__device__ __forceinline__ void mma16816(float* d, const uint32_t* a,
                                         const uint32_t b0, const uint32_t b1) {
    asm volatile(
        "mma.sync.aligned.m16n8k16.row.col.f32.bf16.bf16.f32 "
        "{%0,%1,%2,%3}, {%4,%5,%6,%7}, {%8,%9}, {%0,%1,%2,%3};"
        : "+f"(d[0]), "+f"(d[1]), "+f"(d[2]), "+f"(d[3])
        : "r"(a[0]), "r"(a[1]), "r"(a[2]), "r"(a[3]), "r"(b0), "r"(b1));
}
__device__ __forceinline__ uint32_t pack_bf2(__nv_bfloat16 a, __nv_bfloat16 b) {
    __nv_bfloat162 t; t.x = a; t.y = b;
    return *reinterpret_cast<uint32_t*>(&t);
}

// Shared tile row stride (elements): 32 data + 8 pad -> 80 B rows.
// 80 B stride is a perfect 16B-bank permutation mod 128 -> conflict-free ldmatrix.
#define TSTR 40

// ---------------------------------------------------------------------------
// Transpose + bf16 hi/lo split of weights:  W[K,N] fp32 -> Th/Tl[N,K] bf16
// ---------------------------------------------------------------------------
__global__ __launch_bounds__(256)
void transpose_split_kernel(const float* __restrict__ W,
                            __nv_bfloat16* __restrict__ Th,
                            __nv_bfloat16* __restrict__ Tl,
                            int K, int N)
{
    __shared__ float tile[32][33];
    const int n0 = blockIdx.x * 32;
    const int k0 = blockIdx.y * 32;
    const int tx = threadIdx.x & 31;
    const int ty4 = (threadIdx.x >> 5) * 4;

    #pragma unroll
    for (int j = 0; j < 4; j++)
        tile[ty4 + j][tx] = W[(size_t)(k0 + ty4 + j) * N + n0 + tx];
    __syncthreads();
    #pragma unroll
    for (int j = 0; j < 4; j++) {
        float v = tile[tx][ty4 + j];                 // (k=k0+tx, n=n0+ty4+j)
        __nv_bfloat16 hi = __float2bfloat16_rn(v);
        __nv_bfloat16 lo = __float2bfloat16_rn(v - __bfloat162float(hi));
        size_t o = (size_t)(n0 + ty4 + j) * K + k0 + tx;
        Th[o] = hi;
        Tl[o] = lo;
    }
}

// ---------------------------------------------------------------------------
// Tensor-core GEMM (mma.sync bf16, hi/lo split, fp32 accum):
//   C[M,N] = A[M,K](fp32) @ Bt[N,K]^T + bias
// BM=128, BN=128, BK=32, 256 threads (8 warps, each 64x32).
// ---------------------------------------------------------------------------
__global__ __launch_bounds__(256, 2)
void tc_gemm_kernel(const float* __restrict__ A,
                    const __nv_bfloat16* __restrict__ Bh,
                    const __nv_bfloat16* __restrict__ Bl,
                    const float* __restrict__ bias,
                    float* __restrict__ C,
                    int M, int N, int K)
{
    __shared__ __align__(16) __nv_bfloat16 Ah[128 * TSTR];
    __shared__ __align__(16) __nv_bfloat16 Al[128 * TSTR];
    __shared__ __align__(16) __nv_bfloat16 Bsh[128 * TSTR];
    __shared__ __align__(16) __nv_bfloat16 Bsl[128 * TSTR];

    const int tid  = threadIdx.x;
    const int lane = tid & 31;
    const int wid  = tid >> 5;
    const int brow = blockIdx.y * 128;
    const int bcol = blockIdx.x * 128;

    const int m_base = (wid >> 2) * 64;   // 0 / 64
    const int n_base = (wid & 3) * 32;    // 0..96

    // ldmatrix lane address components (bytes)
    const int a_r  = lane & 15;           // row within 16x16 tile
    const int a_k  = (lane >> 4) * 8;     // k half
    const uint32_t ah_base = smem_u32(Ah) + ((m_base + a_r) * TSTR + a_k) * 2;
    const uint32_t al_base = smem_u32(Al) + ((m_base + a_r) * TSTR + a_k) * 2;
    const int b_n  = (lane >> 4) * 8 + (lane & 7);   // n row within 16-row pair
    const int b_k  = ((lane >> 3) & 1) * 8;          // k half
    const uint32_t bh_base = smem_u32(Bsh) + ((n_base + b_n) * TSTR + b_k) * 2;
    const uint32_t bl_base = smem_u32(Bsl) + ((n_base + b_n) * TSTR + b_k) * 2;

    float acc[4][4][4];
    #pragma unroll
    for (int i = 0; i < 4; i++)
        #pragma unroll
        for (int j = 0; j < 4; j++)
            #pragma unroll
            for (int r = 0; r < 4; r++) acc[i][j][r] = 0.f;

    const int nchunks = K / 32;
    for (int c = 0; c < nchunks; c++) {
        const int k0 = c * 32;

        // --- load A tile [128m x 32k] fp32, split to hi/lo bf16 ---
        #pragma unroll
        for (int i = 0; i < 4; i++) {
            int idx = i * 256 + tid;          // [0,1024)
            int m  = idx >> 3;
            int k4 = (idx & 7) << 2;
            float4 v = *reinterpret_cast<const float4*>(
                &A[(size_t)(brow + m) * K + k0 + k4]);
            __nv_bfloat16 h0 = __float2bfloat16_rn(v.x);
            __nv_bfloat16 h1 = __float2bfloat16_rn(v.y);
            __nv_bfloat16 h2 = __float2bfloat16_rn(v.z);
            __nv_bfloat16 h3 = __float2bfloat16_rn(v.w);
            uint2 hv, lv;
            hv.x = pack_bf2(h0, h1); hv.y = pack_bf2(h2, h3);
            lv.x = pack_bf2(__float2bfloat16_rn(v.x - __bfloat162float(h0)),
                            __float2bfloat16_rn(v.y - __bfloat162float(h1)));
            lv.y = pack_bf2(__float2bfloat16_rn(v.z - __bfloat162float(h2)),
                            __float2bfloat16_rn(v.w - __bfloat162float(h3)));
            *reinterpret_cast<uint2*>(&Ah[m * TSTR + k4]) = hv;
            *reinterpret_cast<uint2*>(&Al[m * TSTR + k4]) = lv;
        }
        // --- load B tiles [128n x 32k] bf16 hi + lo ---
        #pragma unroll
        for (int i = 0; i < 4; i++) {
            int idx = i * 256 + tid;          // [0,1024)
            const __nv_bfloat16* src = (idx < 512) ? Bh : Bl;
            __nv_bfloat16* dst = (idx < 512) ? Bsh : Bsl;
            int j  = idx & 511;
            int r  = j >> 2;
            int k8 = (j & 3) << 3;
            uint4 v = *reinterpret_cast<const uint4*>(
                &src[(size_t)(bcol + r) * K + k0 + k8]);
            *reinterpret_cast<uint4*>(&dst[r * TSTR + k8]) = v;
        }
        __syncthreads();

        #pragma unroll
        for (int ks = 0; ks < 32; ks += 16) {
            uint32_t ah[4][4], al[4][4], bh[2][4], bl[2][4];
            #pragma unroll
            for (int mt = 0; mt < 4; mt++) {
                ldsm_x4(ah[mt], ah_base + (mt * 16 * TSTR + ks) * 2);
                ldsm_x4(al[mt], al_base + (mt * 16 * TSTR + ks) * 2);
            }
            #pragma unroll
            for (int p = 0; p < 2; p++) {
                ldsm_x4(bh[p], bh_base + (p * 16 * TSTR + ks) * 2);
                ldsm_x4(bl[p], bl_base + (p * 16 * TSTR + ks) * 2);
            }
            #pragma unroll
            for (int mt = 0; mt < 4; mt++) {
                #pragma unroll
                for (int nt = 0; nt < 4; nt++) {
                    const int p = nt >> 1, h = (nt & 1) * 2;
                    mma16816(acc[mt][nt], ah[mt], bh[p][h], bh[p][h + 1]);
                    mma16816(acc[mt][nt], ah[mt], bl[p][h], bl[p][h + 1]);
                    mma16816(acc[mt][nt], al[mt], bh[p][h], bh[p][h + 1]);
                }
            }
        }
        __syncthreads();
    }

    // --- epilogue: fragment -> global with bias ---
    #pragma unroll
    for (int nt = 0; nt < 4; nt++) {
        const int ncol = bcol + n_base + nt * 8 + (lane & 3) * 2;
        float2 bv = *reinterpret_cast<const float2*>(&bias[ncol]);
        #pragma unroll
        for (int mt = 0; mt < 4; mt++) {
            int row0 = brow + m_base + mt * 16 + (lane >> 2);
            float2 v0, v1;
            v0.x = acc[mt][nt][0] + bv.x;  v0.y = acc[mt][nt][1] + bv.y;
            v1.x = acc[mt][nt][2] + bv.x;  v1.y = acc[mt][nt][3] + bv.y;
            *reinterpret_cast<float2*>(&C[(size_t)row0 * N + ncol]) = v0;
            *reinterpret_cast<float2*>(&C[(size_t)(row0 + 8) * N + ncol]) = v1;
        }
    }
}

// ---------------------------------------------------------------------------
// Causal flash attention, fp32, one thread per query row (unchanged).
// ---------------------------------------------------------------------------
__global__ __launch_bounds__(128)
void flash_attn_kernel(const float* __restrict__ qkv, float* __restrict__ y)
{
    const int BM = 128, BN = 64;
    __shared__ float ksh[BN][HDD];
    __shared__ float vsh[BN][HDD];

    const int t = threadIdx.x;
    const int qtile = (gridDim.x - 1) - blockIdx.x;
    const int h = blockIdx.y;
    const int b = blockIdx.z;
    const int qi = qtile * BM + t;

    const float* qrow = qkv + ((size_t)(b * SS + qi)) * (3 * DD) + h * HDD;

    float q[HDD], acc[HDD];
    #pragma unroll
    for (int d = 0; d < HDD; d += 4) {
        float4 v = *reinterpret_cast<const float4*>(qrow + d);
        q[d + 0] = v.x * 0.125f;
        q[d + 1] = v.y * 0.125f;
        q[d + 2] = v.z * 0.125f;
        q[d + 3] = v.w * 0.125f;
    }
    #pragma unroll
    for (int d = 0; d < HDD; d++) acc[d] = 0.f;

    float m = -1e30f, l = 0.f;

    const int kv_end = qtile * BM + BM;
    for (int kv0 = 0; kv0 < kv_end; kv0 += BN) {
        #pragma unroll
        for (int i = 0; i < 8; i++) {
            int idx = t + i * 128;
            int r   = idx >> 4;
            int c4  = (idx & 15) << 2;
            const float* kp = qkv + ((size_t)(b * SS + kv0 + r)) * (3 * DD)
                              + DD + h * HDD + c4;
            *reinterpret_cast<float4*>(&ksh[r][c4]) =
                *reinterpret_cast<const float4*>(kp);
            *reinterpret_cast<float4*>(&vsh[r][c4]) =
                *reinterpret_cast<const float4*>(kp + DD);
        }
        __syncthreads();

        int jmax = qi - kv0 + 1;
        if (jmax > BN) jmax = BN;

        for (int j = 0; j < jmax; j++) {
            float s0 = 0.f, s1 = 0.f, s2 = 0.f, s3 = 0.f;
            #pragma unroll
            for (int d = 0; d < HDD; d += 4) {
                float4 kv4 = *reinterpret_cast<const float4*>(&ksh[j][d]);
                s0 = fmaf(q[d + 0], kv4.x, s0);
                s1 = fmaf(q[d + 1], kv4.y, s1);
                s2 = fmaf(q[d + 2], kv4.z, s2);
                s3 = fmaf(q[d + 3], kv4.w, s3);
            }
            float s = (s0 + s1) + (s2 + s3);

            if (s > m) {
                float corr = __expf(m - s);
                l *= corr;
                #pragma unroll
                for (int d = 0; d < HDD; d++) acc[d] *= corr;
                m = s;
            }
            float p = __expf(s - m);
            l += p;
            #pragma unroll
            for (int d = 0; d < HDD; d += 4) {
                float4 vv = *reinterpret_cast<const float4*>(&vsh[j][d]);
                acc[d + 0] = fmaf(p, vv.x, acc[d + 0]);
                acc[d + 1] = fmaf(p, vv.y, acc[d + 1]);
                acc[d + 2] = fmaf(p, vv.z, acc[d + 2]);
                acc[d + 3] = fmaf(p, vv.w, acc[d + 3]);
            }
        }
        __syncthreads();
    }

    float inv = 1.f / l;
    float* yrow = y + ((size_t)(b * SS + qi)) * DD + h * HDD;
    #pragma unroll
    for (int d = 0; d < HDD; d += 4) {
        float4 v;
        v.x = acc[d + 0] * inv;
        v.y = acc[d + 1] * inv;
        v.z = acc[d + 2] * inv;
        v.w = acc[d + 3] * inv;
        *reinterpret_cast<float4*>(yrow + d) = v;
    }
}

// ---------------------------------------------------------------------------
// Launch
// ---------------------------------------------------------------------------
extern "C" void kernel_launch(void* const* d_in, const int* in_sizes, int n_in,
                              void* d_out, int out_size)
{
    const float* x      = (const float*)d_in[0];
    const float* W_attn = (const float*)d_in[1];
    const float* b_attn = (const float*)d_in[2];
    const float* W_proj = (const float*)d_in[3];
    const float* b_proj = (const float*)d_in[4];
    float* out = (float*)d_out;

    static float* qkv_ptr = nullptr;
    static float* y_ptr   = nullptr;
    static __nv_bfloat16 *wt_hi = nullptr, *wt_lo = nullptr;
    static __nv_bfloat16 *wpt_hi = nullptr, *wpt_lo = nullptr;
    if (!qkv_ptr) {   // first (non-captured) correctness call
        cudaGetSymbolAddress((void**)&qkv_ptr, g_qkv);
        cudaGetSymbolAddress((void**)&y_ptr,   g_y);
        cudaGetSymbolAddress((void**)&wt_hi,   g_wt_hi);
        cudaGetSymbolAddress((void**)&wt_lo,   g_wt_lo);
        cudaGetSymbolAddress((void**)&wpt_hi,  g_wpt_hi);
        cudaGetSymbolAddress((void**)&wpt_lo,  g_wpt_lo);
    }

    // 0) transpose + hi/lo split weights
    {
        dim3 g1(3 * DD / 32, DD / 32);
        transpose_split_kernel<<<g1, 256>>>(W_attn, wt_hi, wt_lo, DD, 3 * DD);
        dim3 g2(DD / 32, DD / 32);
        transpose_split_kernel<<<g2, 256>>>(W_proj, wpt_hi, wpt_lo, DD, DD);
    }

    // 1) QKV GEMM (tensor cores): [8192,1024] @ [1024,3072] + b -> g_qkv
    {
        dim3 grid(3 * DD / 128, MTOK / 128);
        tc_gemm_kernel<<<grid, 256>>>(x, wt_hi, wt_lo, b_attn, qkv_ptr,
                                      MTOK, 3 * DD, DD);
    }

    // 2) causal flash attention -> g_y
    {
        dim3 grid(SS / 128, HH, BB);
        flash_attn_kernel<<<grid, 128>>>(qkv_ptr, y_ptr);
    }

    // 3) output projection (tensor cores): [8192,1024] @ [1024,1024] + b -> out
    {
        dim3 grid(DD / 128, MTOK / 128);
        tc_gemm_kernel<<<grid, 256>>>(y_ptr, wpt_hi, wpt_lo, b_proj, out,
                                      MTOK, DD, DD);
    }
}

// round 4
// speedup vs baseline: 3.3157x; 2.2220x over previous
#include <cuda_runtime.h>
#include <cuda_bf16.h>
#include <cstdint>
#include <cstddef>

// Problem constants
#define BB  4
#define SS  2048
#define DD  1024
#define HH  16
#define HDD 64
#define MTOK (BB*SS)          // 8192 token rows

// q prescale: HD^-0.5 * log2(e)  (softmax done in exp2 domain)
#define QSC 0.18033688011112042f

// Scratch (device globals; no allocations allowed)
__device__ __align__(128) float g_y[(size_t)MTOK * DD];                 // [8192,1024]
__device__ __align__(128) __nv_bfloat16 g_wt_hi [(size_t)3 * DD * DD];
__device__ __align__(128) __nv_bfloat16 g_wt_lo [(size_t)3 * DD * DD];
__device__ __align__(128) __nv_bfloat16 g_wpt_hi[(size_t)DD * DD];
__device__ __align__(128) __nv_bfloat16 g_wpt_lo[(size_t)DD * DD];
// split Q/K/V, layout [b*H+h][s][64]
#define BHSZ ((size_t)BB * HH * SS * HDD)
__device__ __align__(128) __nv_bfloat16 g_qh[BHSZ], g_ql[BHSZ];
__device__ __align__(128) __nv_bfloat16 g_kh[BHSZ], g_kl[BHSZ];
__device__ __align__(128) __nv_bfloat16 g_vh[BHSZ], g_vl[BHSZ];

// ---------------------------------------------------------------------------
// Warp-MMA helpers (sm_80+ path: ldmatrix + mma.sync)
// ---------------------------------------------------------------------------
__device__ __forceinline__ uint32_t smem_u32(const void* p) {
    uint32_t a;
    asm("{ .reg .u64 t; cvta.to.shared.u64 t, %1; cvt.u32.u64 %0, t; }"
        : "=r"(a) : "l"(p));
    return a;
}
__device__ __forceinline__ void ldsm_x4(uint32_t* r, uint32_t addr) {
    asm volatile("ldmatrix.sync.aligned.m8n8.x4.shared.b16 {%0,%1,%2,%3}, [%4];"
                 : "=r"(r[0]), "=r"(r[1]), "=r"(r[2]), "=r"(r[3]) : "r"(addr));
}
__device__ __forceinline__ void ldsm_x4_t(uint32_t* r, uint32_t addr) {
    asm volatile("ldmatrix.sync.aligned.m8n8.x4.trans.shared.b16 {%0,%1,%2,%3}, [%4];"
                 : "=r"(r[0]), "=r"(r[1]), "=r"(r[2]), "=r"(r[3]) : "r"(addr));
}
__device__ __forceinline__ void mma16816(float* d, const uint32_t* a,
                                         const uint32_t b0, const uint32_t b1) {
    asm volatile(
        "mma.sync.aligned.m16n8k16.row.col.f32.bf16.bf16.f32 "
        "{%0,%1,%2,%3}, {%4,%5,%6,%7}, {%8,%9}, {%0,%1,%2,%3};"
        : "+f"(d[0]), "+f"(d[1]), "+f"(d[2]), "+f"(d[3])
        : "r"(a[0]), "r"(a[1]), "r"(a[2]), "r"(a[3]), "r"(b0), "r"(b1));
}
__device__ __forceinline__ uint32_t pack_bf2(__nv_bfloat16 a, __nv_bfloat16 b) {
    __nv_bfloat162 t; t.x = a; t.y = b;
    return *reinterpret_cast<uint32_t*>(&t);
}
__device__ __forceinline__ float ex2f(float x) {
    float r;
    asm("ex2.approx.f32 %0, %1;" : "=f"(r) : "f"(x));
    return r;
}

// GEMM shared tile stride: 32 data + 8 pad elems (80B rows, conflict-free)
#define TSTR 40
// Attention shared tile stride: 64 data + 8 pad elems (144B rows, conflict-free)
#define KSTR 72

// ---------------------------------------------------------------------------
// Transpose + bf16 hi/lo split of weights:  W[K,N] fp32 -> Th/Tl[N,K] bf16
// ---------------------------------------------------------------------------
__global__ __launch_bounds__(256)
void transpose_split_kernel(const float* __restrict__ W,
                            __nv_bfloat16* __restrict__ Th,
                            __nv_bfloat16* __restrict__ Tl,
                            int K, int N)
{
    __shared__ float tile[32][33];
    const int n0 = blockIdx.x * 32;
    const int k0 = blockIdx.y * 32;
    const int tx = threadIdx.x & 31;
    const int ty4 = (threadIdx.x >> 5) * 4;

    #pragma unroll
    for (int j = 0; j < 4; j++)
        tile[ty4 + j][tx] = W[(size_t)(k0 + ty4 + j) * N + n0 + tx];
    __syncthreads();
    #pragma unroll
    for (int j = 0; j < 4; j++) {
        float v = tile[tx][ty4 + j];
        __nv_bfloat16 hi = __float2bfloat16_rn(v);
        __nv_bfloat16 lo = __float2bfloat16_rn(v - __bfloat162float(hi));
        size_t o = (size_t)(n0 + ty4 + j) * K + k0 + tx;
        Th[o] = hi;
        Tl[o] = lo;
    }
}

// ---------------------------------------------------------------------------
// Tensor-core GEMM (mma.sync bf16, hi/lo split, fp32 accum):
//   C[M,N] = A[M,K](fp32) @ Bt[N,K]^T + bias
// MODE 0: write fp32 C.   MODE 1 (QKV): write split bf16 q/k/v buffers.
// ---------------------------------------------------------------------------
template <int MODE>
__global__ __launch_bounds__(256, 2)
void tc_gemm_kernel(const float* __restrict__ A,
                    const __nv_bfloat16* __restrict__ Bh,
                    const __nv_bfloat16* __restrict__ Bl,
                    const float* __restrict__ bias,
                    float* __restrict__ C,
                    __nv_bfloat16* __restrict__ oqh, __nv_bfloat16* __restrict__ oql,
                    __nv_bfloat16* __restrict__ okh, __nv_bfloat16* __restrict__ okl,
                    __nv_bfloat16* __restrict__ ovh, __nv_bfloat16* __restrict__ ovl,
                    int M, int N, int K)
{
    __shared__ __align__(16) __nv_bfloat16 Ah[128 * TSTR];
    __shared__ __align__(16) __nv_bfloat16 Al[128 * TSTR];
    __shared__ __align__(16) __nv_bfloat16 Bsh[128 * TSTR];
    __shared__ __align__(16) __nv_bfloat16 Bsl[128 * TSTR];

    const int tid  = threadIdx.x;
    const int lane = tid & 31;
    const int wid  = tid >> 5;
    const int brow = blockIdx.y * 128;
    const int bcol = blockIdx.x * 128;

    const int m_base = (wid >> 2) * 64;
    const int n_base = (wid & 3) * 32;

    const int a_r  = lane & 15;
    const int a_k  = (lane >> 4) * 8;
    const uint32_t ah_base = smem_u32(Ah) + ((m_base + a_r) * TSTR + a_k) * 2;
    const uint32_t al_base = smem_u32(Al) + ((m_base + a_r) * TSTR + a_k) * 2;
    const int b_n  = (lane >> 4) * 8 + (lane & 7);
    const int b_k  = ((lane >> 3) & 1) * 8;
    const uint32_t bh_base = smem_u32(Bsh) + ((n_base + b_n) * TSTR + b_k) * 2;
    const uint32_t bl_base = smem_u32(Bsl) + ((n_base + b_n) * TSTR + b_k) * 2;

    float acc[4][4][4];
    #pragma unroll
    for (int i = 0; i < 4; i++)
        #pragma unroll
        for (int j = 0; j < 4; j++)
            #pragma unroll
            for (int r = 0; r < 4; r++) acc[i][j][r] = 0.f;

    const int nchunks = K / 32;
    for (int c = 0; c < nchunks; c++) {
        const int k0 = c * 32;

        #pragma unroll
        for (int i = 0; i < 4; i++) {
            int idx = i * 256 + tid;
            int m  = idx >> 3;
            int k4 = (idx & 7) << 2;
            float4 v = *reinterpret_cast<const float4*>(
                &A[(size_t)(brow + m) * K + k0 + k4]);
            __nv_bfloat16 h0 = __float2bfloat16_rn(v.x);
            __nv_bfloat16 h1 = __float2bfloat16_rn(v.y);
            __nv_bfloat16 h2 = __float2bfloat16_rn(v.z);
            __nv_bfloat16 h3 = __float2bfloat16_rn(v.w);
            uint2 hv, lv;
            hv.x = pack_bf2(h0, h1); hv.y = pack_bf2(h2, h3);
            lv.x = pack_bf2(__float2bfloat16_rn(v.x - __bfloat162float(h0)),
                            __float2bfloat16_rn(v.y - __bfloat162float(h1)));
            lv.y = pack_bf2(__float2bfloat16_rn(v.z - __bfloat162float(h2)),
                            __float2bfloat16_rn(v.w - __bfloat162float(h3)));
            *reinterpret_cast<uint2*>(&Ah[m * TSTR + k4]) = hv;
            *reinterpret_cast<uint2*>(&Al[m * TSTR + k4]) = lv;
        }
        #pragma unroll
        for (int i = 0; i < 4; i++) {
            int idx = i * 256 + tid;
            const __nv_bfloat16* src = (idx < 512) ? Bh : Bl;
            __nv_bfloat16* dst = (idx < 512) ? Bsh : Bsl;
            int j  = idx & 511;
            int r  = j >> 2;
            int k8 = (j & 3) << 3;
            uint4 v = *reinterpret_cast<const uint4*>(
                &src[(size_t)(bcol + r) * K + k0 + k8]);
            *reinterpret_cast<uint4*>(&dst[r * TSTR + k8]) = v;
        }
        __syncthreads();

        #pragma unroll
        for (int ks = 0; ks < 32; ks += 16) {
            uint32_t ah[4][4], al[4][4], bh[2][4], bl[2][4];
            #pragma unroll
            for (int mt = 0; mt < 4; mt++) {
                ldsm_x4(ah[mt], ah_base + (mt * 16 * TSTR + ks) * 2);
                ldsm_x4(al[mt], al_base + (mt * 16 * TSTR + ks) * 2);
            }
            #pragma unroll
            for (int p = 0; p < 2; p++) {
                ldsm_x4(bh[p], bh_base + (p * 16 * TSTR + ks) * 2);
                ldsm_x4(bl[p], bl_base + (p * 16 * TSTR + ks) * 2);
            }
            #pragma unroll
            for (int mt = 0; mt < 4; mt++) {
                #pragma unroll
                for (int nt = 0; nt < 4; nt++) {
                    const int p = nt >> 1, h = (nt & 1) * 2;
                    mma16816(acc[mt][nt], ah[mt], bh[p][h], bh[p][h + 1]);
                    mma16816(acc[mt][nt], ah[mt], bl[p][h], bl[p][h + 1]);
                    mma16816(acc[mt][nt], al[mt], bh[p][h], bh[p][h + 1]);
                }
            }
        }
        __syncthreads();
    }

    // --- epilogue ---
    #pragma unroll
    for (int nt = 0; nt < 4; nt++) {
        const int ncol = bcol + n_base + nt * 8 + (lane & 3) * 2;
        float2 bv = *reinterpret_cast<const float2*>(&bias[ncol]);
        if (MODE == 0) {
            #pragma unroll
            for (int mt = 0; mt < 4; mt++) {
                int row0 = brow + m_base + mt * 16 + (lane >> 2);
                float2 v0, v1;
                v0.x = acc[mt][nt][0] + bv.x;  v0.y = acc[mt][nt][1] + bv.y;
                v1.x = acc[mt][nt][2] + bv.x;  v1.y = acc[mt][nt][3] + bv.y;
                *reinterpret_cast<float2*>(&C[(size_t)row0 * N + ncol]) = v0;
                *reinterpret_cast<float2*>(&C[(size_t)(row0 + 8) * N + ncol]) = v1;
            }
        } else {
            // QKV split epilogue: ncol -> (region, head, dim)
            const int region = ncol >> 10;
            const int hh = (ncol >> 6) & (HH - 1);
            const int dd = ncol & (HDD - 1);
            __nv_bfloat16* oh = (region == 0) ? oqh : (region == 1) ? okh : ovh;
            __nv_bfloat16* ol = (region == 0) ? oql : (region == 1) ? okl : ovl;
            const float sc = (region == 0) ? QSC : 1.f;
            const size_t colbase = (size_t)hh * (SS * HDD) + dd;
            #pragma unroll
            for (int mt = 0; mt < 4; mt++) {
                int row0 = brow + m_base + mt * 16 + (lane >> 2);
                #pragma unroll
                for (int rr = 0; rr < 2; rr++) {
                    int row = row0 + rr * 8;
                    float v0 = (acc[mt][nt][rr * 2 + 0] + bv.x) * sc;
                    float v1 = (acc[mt][nt][rr * 2 + 1] + bv.y) * sc;
                    __nv_bfloat16 h0 = __float2bfloat16_rn(v0);
                    __nv_bfloat16 h1 = __float2bfloat16_rn(v1);
                    __nv_bfloat16 l0 = __float2bfloat16_rn(v0 - __bfloat162float(h0));
                    __nv_bfloat16 l1 = __float2bfloat16_rn(v1 - __bfloat162float(h1));
                    int bb = row >> 11, ss = row & (SS - 1);
                    size_t off = (size_t)bb * HH * SS * HDD + colbase + (size_t)ss * HDD;
                    *reinterpret_cast<uint32_t*>(&oh[off]) = pack_bf2(h0, h1);
                    *reinterpret_cast<uint32_t*>(&ol[off]) = pack_bf2(l0, l1);
                }
            }
        }
    }
}

// ---------------------------------------------------------------------------
// Tensor-core causal flash attention.
// CTA: 64 query rows of one (b,h); 4 warps x 16 rows. 64 keys per iteration.
// S = Q K^T via mma (hi/lo bf16, fp32 accum); online softmax in fragments;
// P hi/lo re-split in registers; O += P V via mma with ldmatrix.trans V frags.
// Writes y [token][h*64+d] fp32 normalized.
// ---------------------------------------------------------------------------
#define SM_QH 0
#define SM_QL (64*KSTR*2)
#define SM_KH (2*64*KSTR*2)
#define SM_KL (3*64*KSTR*2)
#define SM_VH (4*64*KSTR*2)
#define SM_VL (5*64*KSTR*2)
#define SM_ATT_TOTAL (6*64*KSTR*2)   // 55296 bytes

__global__ __launch_bounds__(128)
void flash_attn_tc(const __nv_bfloat16* __restrict__ Qh, const __nv_bfloat16* __restrict__ Ql,
                   const __nv_bfloat16* __restrict__ Kh, const __nv_bfloat16* __restrict__ Kl,
                   const __nv_bfloat16* __restrict__ Vh, const __nv_bfloat16* __restrict__ Vl,
                   float* __restrict__ y)
{
    extern __shared__ __align__(16) char sm[];
    const uint32_t sbase = smem_u32(sm);

    const int tid  = threadIdx.x;
    const int lane = tid & 31;
    const int w    = tid >> 5;
    const int qtile = (gridDim.x - 1) - blockIdx.x;   // long tiles first
    const int h = blockIdx.y;
    const int b = blockIdx.z;
    const size_t base = ((size_t)(b * HH + h)) * SS * HDD;

    // cooperative tile load indices: 512 uint4 per 64x64 bf16 buffer
    const int ld_r  = (tid * 4) >> 3;        // covers rows via 4 iters
    // (computed inline below)

    // ---- load Q tile (once) ----
    {
        const int s0 = qtile * 64;
        #pragma unroll
        for (int i = 0; i < 4; i++) {
            int idx = i * 128 + tid;
            int r  = idx >> 3;
            int c8 = (idx & 7) * 8;
            *reinterpret_cast<uint4*>(sm + SM_QH + (r * KSTR + c8) * 2) =
                *reinterpret_cast<const uint4*>(&Qh[base + (size_t)(s0 + r) * HDD + c8]);
            *reinterpret_cast<uint4*>(sm + SM_QL + (r * KSTR + c8) * 2) =
                *reinterpret_cast<const uint4*>(&Ql[base + (size_t)(s0 + r) * HDD + c8]);
        }
    }
    __syncthreads();

    // ---- Q fragments (hoisted) ----
    uint32_t qfh[4][4], qfl[4][4];
    {
        const uint32_t qa = sbase + SM_QH +
            ((w * 16 + (lane & 15)) * KSTR + (lane >> 4) * 8) * 2;
        const uint32_t ql_ = qa + (SM_QL - SM_QH);
        #pragma unroll
        for (int kc = 0; kc < 4; kc++) {
            ldsm_x4(qfh[kc], qa  + kc * 32);
            ldsm_x4(qfl[kc], ql_ + kc * 32);
        }
    }
    __syncthreads();   // Q smem no longer needed (frags held)

    // K B-frag / V B-frag(trans) per-thread base offsets
    const uint32_t ka_h = sbase + SM_KH +
        (((lane >> 4) * 8 + (lane & 7)) * KSTR + ((lane >> 3) & 1) * 8) * 2;
    const uint32_t ka_l = ka_h + (SM_KL - SM_KH);
    const uint32_t va_h = sbase + SM_VH +
        ((((lane >> 3) & 1) * 8 + (lane & 7)) * KSTR + ((lane >> 4) & 1) * 8) * 2;
    const uint32_t va_l = va_h + (SM_VL - SM_VH);

    float o[8][4];
    #pragma unroll
    for (int j = 0; j < 8; j++)
        #pragma unroll
        for (int r = 0; r < 4; r++) o[j][r] = 0.f;
    float m0 = -1e30f, m1 = -1e30f, l0 = 0.f, l1 = 0.f;

    const int row_a0 = qtile * 64 + w * 16 + (lane >> 2);   // abs q row (g)
    (void)ld_r;

    for (int kv = 0; kv <= qtile; kv++) {
        // ---- load K/V tiles (hi+lo) ----
        const int s0 = kv * 64;
        #pragma unroll
        for (int i = 0; i < 4; i++) {
            int idx = i * 128 + tid;
            int r  = idx >> 3;
            int c8 = (idx & 7) * 8;
            size_t go = base + (size_t)(s0 + r) * HDD + c8;
            uint32_t so = (r * KSTR + c8) * 2;
            *reinterpret_cast<uint4*>(sm + SM_KH + so) =
                *reinterpret_cast<const uint4*>(&Kh[go]);
            *reinterpret_cast<uint4*>(sm + SM_KL + so) =
                *reinterpret_cast<const uint4*>(&Kl[go]);
            *reinterpret_cast<uint4*>(sm + SM_VH + so) =
                *reinterpret_cast<const uint4*>(&Vh[go]);
            *reinterpret_cast<uint4*>(sm + SM_VL + so) =
                *reinterpret_cast<const uint4*>(&Vl[go]);
        }
        __syncthreads();

        // ---- S = Q K^T ----
        float s[8][4];
        #pragma unroll
        for (int j = 0; j < 8; j++)
            #pragma unroll
            for (int r = 0; r < 4; r++) s[j][r] = 0.f;

        #pragma unroll
        for (int kc = 0; kc < 4; kc++) {
            #pragma unroll
            for (int np = 0; np < 4; np++) {
                uint32_t kh4[4], kl4[4];
                ldsm_x4(kh4, ka_h + np * (16 * KSTR * 2) + kc * 32);
                ldsm_x4(kl4, ka_l + np * (16 * KSTR * 2) + kc * 32);
                mma16816(s[2*np],   qfh[kc], kh4[0], kh4[1]);
                mma16816(s[2*np],   qfl[kc], kh4[0], kh4[1]);
                mma16816(s[2*np],   qfh[kc], kl4[0], kl4[1]);
                mma16816(s[2*np+1], qfh[kc], kh4[2], kh4[3]);
                mma16816(s[2*np+1], qfl[kc], kh4[2], kh4[3]);
                mma16816(s[2*np+1], qfh[kc], kl4[2], kl4[3]);
            }
        }

        // ---- causal mask (diagonal tile only) ----
        if (kv == qtile) {
            #pragma unroll
            for (int j = 0; j < 8; j++) {
                int col = kv * 64 + j * 8 + (lane & 3) * 2;
                #pragma unroll
                for (int r = 0; r < 4; r++) {
                    int cc = col + (r & 1);
                    int rw = row_a0 + ((r >= 2) ? 8 : 0);
                    if (cc > rw) s[j][r] = -1e30f;
                }
            }
        }

        // ---- online softmax ----
        float mx0 = -1e30f, mx1 = -1e30f;
        #pragma unroll
        for (int j = 0; j < 8; j++) {
            mx0 = fmaxf(mx0, fmaxf(s[j][0], s[j][1]));
            mx1 = fmaxf(mx1, fmaxf(s[j][2], s[j][3]));
        }
        mx0 = fmaxf(mx0, __shfl_xor_sync(0xffffffffu, mx0, 1));
        mx0 = fmaxf(mx0, __shfl_xor_sync(0xffffffffu, mx0, 2));
        mx1 = fmaxf(mx1, __shfl_xor_sync(0xffffffffu, mx1, 1));
        mx1 = fmaxf(mx1, __shfl_xor_sync(0xffffffffu, mx1, 2));
        float mn0 = fmaxf(m0, mx0), mn1 = fmaxf(m1, mx1);
        float sc0 = ex2f(m0 - mn0), sc1 = ex2f(m1 - mn1);
        m0 = mn0; m1 = mn1;
        l0 *= sc0; l1 *= sc1;
        #pragma unroll
        for (int j = 0; j < 8; j++) {
            o[j][0] *= sc0; o[j][1] *= sc0;
            o[j][2] *= sc1; o[j][3] *= sc1;
        }
        // p = exp2(s - m); accumulate l
        #pragma unroll
        for (int j = 0; j < 8; j++) {
            float p0 = ex2f(s[j][0] - mn0);
            float p1 = ex2f(s[j][1] - mn0);
            float p2 = ex2f(s[j][2] - mn1);
            float p3 = ex2f(s[j][3] - mn1);
            s[j][0] = p0; s[j][1] = p1; s[j][2] = p2; s[j][3] = p3;
            l0 += p0 + p1;
            l1 += p2 + p3;
        }

        // ---- O += P V ----
        #pragma unroll
        for (int kc = 0; kc < 4; kc++) {
            // A-frags for keys 16kc..16kc+15 from p (S ntiles 2kc, 2kc+1)
            uint32_t aph[4], apl[4];
            #pragma unroll
            for (int t2 = 0; t2 < 2; t2++) {
                int j = 2 * kc + t2;
                __nv_bfloat16 h0 = __float2bfloat16_rn(s[j][0]);
                __nv_bfloat16 h1 = __float2bfloat16_rn(s[j][1]);
                __nv_bfloat16 h2 = __float2bfloat16_rn(s[j][2]);
                __nv_bfloat16 h3 = __float2bfloat16_rn(s[j][3]);
                aph[t2*2 + 0] = pack_bf2(h0, h1);
                aph[t2*2 + 1] = pack_bf2(h2, h3);
                apl[t2*2 + 0] = pack_bf2(
                    __float2bfloat16_rn(s[j][0] - __bfloat162float(h0)),
                    __float2bfloat16_rn(s[j][1] - __bfloat162float(h1)));
                apl[t2*2 + 1] = pack_bf2(
                    __float2bfloat16_rn(s[j][2] - __bfloat162float(h2)),
                    __float2bfloat16_rn(s[j][3] - __bfloat162float(h3)));
            }
            #pragma unroll
            for (int nb = 0; nb < 4; nb++) {
                uint32_t vh4[4], vl4[4];
                ldsm_x4_t(vh4, va_h + kc * (16 * KSTR * 2) + nb * 32);
                ldsm_x4_t(vl4, va_l + kc * (16 * KSTR * 2) + nb * 32);
                mma16816(o[2*nb],   aph, vh4[0], vh4[1]);
                mma16816(o[2*nb],   apl, vh4[0], vh4[1]);
                mma16816(o[2*nb],   aph, vl4[0], vl4[1]);
                mma16816(o[2*nb+1], aph, vh4[2], vh4[3]);
                mma16816(o[2*nb+1], apl, vh4[2], vh4[3]);
                mma16816(o[2*nb+1], aph, vl4[2], vl4[3]);
            }
        }
        __syncthreads();
    }

    // ---- epilogue: normalize + write ----
    l0 += __shfl_xor_sync(0xffffffffu, l0, 1);
    l0 += __shfl_xor_sync(0xffffffffu, l0, 2);
    l1 += __shfl_xor_sync(0xffffffffu, l1, 1);
    l1 += __shfl_xor_sync(0xffffffffu, l1, 2);
    float inv0 = 1.f / l0, inv1 = 1.f / l1;

    size_t tok0 = (size_t)b * SS + row_a0;
    float* y0 = y + tok0 * DD + h * HDD + (lane & 3) * 2;
    float* y1 = y0 + (size_t)8 * DD;
    #pragma unroll
    for (int j = 0; j < 8; j++) {
        float2 v0, v1;
        v0.x = o[j][0] * inv0; v0.y = o[j][1] * inv0;
        v1.x = o[j][2] * inv1; v1.y = o[j][3] * inv1;
        *reinterpret_cast<float2*>(y0 + j * 8) = v0;
        *reinterpret_cast<float2*>(y1 + j * 8) = v1;
    }
}

// ---------------------------------------------------------------------------
// Launch
// ---------------------------------------------------------------------------
extern "C" void kernel_launch(void* const* d_in, const int* in_sizes, int n_in,
                              void* d_out, int out_size)
{
    const float* x      = (const float*)d_in[0];
    const float* W_attn = (const float*)d_in[1];
    const float* b_attn = (const float*)d_in[2];
    const float* W_proj = (const float*)d_in[3];
    const float* b_proj = (const float*)d_in[4];
    float* out = (float*)d_out;

    static float* y_ptr = nullptr;
    static __nv_bfloat16 *wt_hi, *wt_lo, *wpt_hi, *wpt_lo;
    static __nv_bfloat16 *qh, *ql, *kh, *kl, *vh, *vl;
    if (!y_ptr) {   // first (non-captured) correctness call
        cudaGetSymbolAddress((void**)&y_ptr,  g_y);
        cudaGetSymbolAddress((void**)&wt_hi,  g_wt_hi);
        cudaGetSymbolAddress((void**)&wt_lo,  g_wt_lo);
        cudaGetSymbolAddress((void**)&wpt_hi, g_wpt_hi);
        cudaGetSymbolAddress((void**)&wpt_lo, g_wpt_lo);
        cudaGetSymbolAddress((void**)&qh, g_qh);
        cudaGetSymbolAddress((void**)&ql, g_ql);
        cudaGetSymbolAddress((void**)&kh, g_kh);
        cudaGetSymbolAddress((void**)&kl, g_kl);
        cudaGetSymbolAddress((void**)&vh, g_vh);
        cudaGetSymbolAddress((void**)&vl, g_vl);
        cudaFuncSetAttribute(flash_attn_tc,
                             cudaFuncAttributeMaxDynamicSharedMemorySize,
                             SM_ATT_TOTAL);
    }

    // 0) transpose + hi/lo split weights
    {
        dim3 g1(3 * DD / 32, DD / 32);
        transpose_split_kernel<<<g1, 256>>>(W_attn, wt_hi, wt_lo, DD, 3 * DD);
        dim3 g2(DD / 32, DD / 32);
        transpose_split_kernel<<<g2, 256>>>(W_proj, wpt_hi, wpt_lo, DD, DD);
    }

    // 1) QKV GEMM + fused split epilogue -> q/k/v hi,lo bf16 per-head buffers
    {
        dim3 grid(3 * DD / 128, MTOK / 128);
        tc_gemm_kernel<1><<<grid, 256>>>(x, wt_hi, wt_lo, b_attn, nullptr,
                                         qh, ql, kh, kl, vh, vl,
                                         MTOK, 3 * DD, DD);
    }

    // 2) tensor-core causal flash attention -> g_y
    {
        dim3 grid(SS / 64, HH, BB);
        flash_attn_tc<<<grid, 128, SM_ATT_TOTAL>>>(qh, ql, kh, kl, vh, vl, y_ptr);
    }

    // 3) output projection -> out
    {
        dim3 grid(DD / 128, MTOK / 128);
        tc_gemm_kernel<0><<<grid, 256>>>(y_ptr, wpt_hi, wpt_lo, b_proj, out,
                                         nullptr, nullptr, nullptr, nullptr,
                                         nullptr, nullptr,
                                         MTOK, DD, DD);
    }
}

// round 5
// speedup vs baseline: 3.4061x; 1.0272x over previous
#include <cuda_runtime.h>
#include <cuda_bf16.h>
#include <cstdint>
#include <cstddef>

// Problem constants
#define BB  4
#define SS  2048
#define DD  1024
#define HH  16
#define HDD 64
#define MTOK (BB*SS)          // 8192 token rows

// q prescale: HD^-0.5 * log2(e)  (softmax done in exp2 domain)
#define QSC 0.18033688011112042f

// Scratch (device globals; no allocations allowed)
__device__ __align__(128) __nv_bfloat16 g_xh[(size_t)MTOK * DD];   // x split hi
__device__ __align__(128) __nv_bfloat16 g_xl[(size_t)MTOK * DD];   // x split lo
__device__ __align__(128) __nv_bfloat16 g_yh[(size_t)MTOK * DD];   // attn out hi
__device__ __align__(128) __nv_bfloat16 g_yl[(size_t)MTOK * DD];   // attn out lo
__device__ __align__(128) __nv_bfloat16 g_wt_hi [(size_t)3 * DD * DD];
__device__ __align__(128) __nv_bfloat16 g_wt_lo [(size_t)3 * DD * DD];
__device__ __align__(128) __nv_bfloat16 g_wpt_hi[(size_t)DD * DD];
__device__ __align__(128) __nv_bfloat16 g_wpt_lo[(size_t)DD * DD];
// split Q/K/V, layout [b*H+h][s][64]
#define BHSZ ((size_t)BB * HH * SS * HDD)
__device__ __align__(128) __nv_bfloat16 g_qh[BHSZ], g_ql[BHSZ];
__device__ __align__(128) __nv_bfloat16 g_kh[BHSZ], g_kl[BHSZ];
__device__ __align__(128) __nv_bfloat16 g_vh[BHSZ], g_vl[BHSZ];

// ---------------------------------------------------------------------------
// Warp-MMA + async-copy helpers (sm_80+ path; compiles on compute_103)
// ---------------------------------------------------------------------------
__device__ __forceinline__ uint32_t smem_u32(const void* p) {
    uint32_t a;
    asm("{ .reg .u64 t; cvta.to.shared.u64 t, %1; cvt.u32.u64 %0, t; }"
        : "=r"(a) : "l"(p));
    return a;
}
__device__ __forceinline__ void ldsm_x4(uint32_t* r, uint32_t addr) {
    asm volatile("ldmatrix.sync.aligned.m8n8.x4.shared.b16 {%0,%1,%2,%3}, [%4];"
                 : "=r"(r[0]), "=r"(r[1]), "=r"(r[2]), "=r"(r[3]) : "r"(addr));
}
__device__ __forceinline__ void ldsm_x4_t(uint32_t* r, uint32_t addr) {
    asm volatile("ldmatrix.sync.aligned.m8n8.x4.trans.shared.b16 {%0,%1,%2,%3}, [%4];"
                 : "=r"(r[0]), "=r"(r[1]), "=r"(r[2]), "=r"(r[3]) : "r"(addr));
}
__device__ __forceinline__ void mma16816(float* d, const uint32_t* a,
                                         const uint32_t b0, const uint32_t b1) {
    asm volatile(
        "mma.sync.aligned.m16n8k16.row.col.f32.bf16.bf16.f32 "
        "{%0,%1,%2,%3}, {%4,%5,%6,%7}, {%8,%9}, {%0,%1,%2,%3};"
        : "+f"(d[0]), "+f"(d[1]), "+f"(d[2]), "+f"(d[3])
        : "r"(a[0]), "r"(a[1]), "r"(a[2]), "r"(a[3]), "r"(b0), "r"(b1));
}
__device__ __forceinline__ void cp_async16(uint32_t saddr, const void* g) {
    asm volatile("cp.async.cg.shared.global [%0], [%1], 16;"
                 :: "r"(saddr), "l"(g) : "memory");
}
#define CP_COMMIT() asm volatile("cp.async.commit_group;" ::: "memory")
#define CP_WAIT(n)  asm volatile("cp.async.wait_group %0;" :: "n"(n) : "memory")

__device__ __forceinline__ uint32_t pack_bf2(__nv_bfloat16 a, __nv_bfloat16 b) {
    __nv_bfloat162 t; t.x = a; t.y = b;
    return *reinterpret_cast<uint32_t*>(&t);
}
__device__ __forceinline__ float ex2f(float x) {
    float r;
    asm("ex2.approx.f32 %0, %1;" : "=f"(r) : "f"(x));
    return r;
}

// GEMM shared tile stride: 32 data + 8 pad elems (80B rows, conflict-free)
#define TSTR 40
// Attention shared tile stride: 64 data + 8 pad elems (144B rows, conflict-free)
#define KSTR 72

// ---------------------------------------------------------------------------
// Elementwise fp32 -> bf16 hi/lo split (for x)
// ---------------------------------------------------------------------------
__global__ __launch_bounds__(256)
void split_kernel(const float* __restrict__ in,
                  __nv_bfloat16* __restrict__ hi,
                  __nv_bfloat16* __restrict__ lo)
{
    size_t i = ((size_t)blockIdx.x * 256 + threadIdx.x) * 4;
    float4 v = *reinterpret_cast<const float4*>(in + i);
    __nv_bfloat16 h0 = __float2bfloat16_rn(v.x);
    __nv_bfloat16 h1 = __float2bfloat16_rn(v.y);
    __nv_bfloat16 h2 = __float2bfloat16_rn(v.z);
    __nv_bfloat16 h3 = __float2bfloat16_rn(v.w);
    uint2 hv, lv;
    hv.x = pack_bf2(h0, h1); hv.y = pack_bf2(h2, h3);
    lv.x = pack_bf2(__float2bfloat16_rn(v.x - __bfloat162float(h0)),
                    __float2bfloat16_rn(v.y - __bfloat162float(h1)));
    lv.y = pack_bf2(__float2bfloat16_rn(v.z - __bfloat162float(h2)),
                    __float2bfloat16_rn(v.w - __bfloat162float(h3)));
    *reinterpret_cast<uint2*>(hi + i) = hv;
    *reinterpret_cast<uint2*>(lo + i) = lv;
}

// ---------------------------------------------------------------------------
// Transpose + bf16 hi/lo split of weights:  W[K,N] fp32 -> Th/Tl[N,K] bf16
// ---------------------------------------------------------------------------
__global__ __launch_bounds__(256)
void transpose_split_kernel(const float* __restrict__ W,
                            __nv_bfloat16* __restrict__ Th,
                            __nv_bfloat16* __restrict__ Tl,
                            int K, int N)
{
    __shared__ float tile[32][33];
    const int n0 = blockIdx.x * 32;
    const int k0 = blockIdx.y * 32;
    const int tx = threadIdx.x & 31;
    const int ty4 = (threadIdx.x >> 5) * 4;

    #pragma unroll
    for (int j = 0; j < 4; j++)
        tile[ty4 + j][tx] = W[(size_t)(k0 + ty4 + j) * N + n0 + tx];
    __syncthreads();
    #pragma unroll
    for (int j = 0; j < 4; j++) {
        float v = tile[tx][ty4 + j];
        __nv_bfloat16 hi = __float2bfloat16_rn(v);
        __nv_bfloat16 lo = __float2bfloat16_rn(v - __bfloat162float(hi));
        size_t o = (size_t)(n0 + ty4 + j) * K + k0 + tx;
        Th[o] = hi;
        Tl[o] = lo;
    }
}

// ---------------------------------------------------------------------------
// cp.async double-buffered tensor-core GEMM (bf16 hi/lo, fp32 accum):
//   C[M,N] = (Ah+Al)[M,K] @ (Bh+Bl)[N,K]^T + bias
// BM=128, BN=128, BK=32, 256 threads (8 warps, each 64x32), 2 stages.
// MODE 0: fp32 C.  MODE 1 (QKV): split bf16 q/k/v per-head buffers.
// ---------------------------------------------------------------------------
#define STG_BYTES (4 * 128 * TSTR * 2)    // 40960 per stage
#define ARR_BYTES (128 * TSTR * 2)        // 10240 per array
#define GEMM_SMEM (2 * STG_BYTES)         // 81920

template <int MODE>
__global__ __launch_bounds__(256, 2)
void tc_gemm_kernel(const __nv_bfloat16* __restrict__ Agh,
                    const __nv_bfloat16* __restrict__ Agl,
                    const __nv_bfloat16* __restrict__ Bh,
                    const __nv_bfloat16* __restrict__ Bl,
                    const float* __restrict__ bias,
                    float* __restrict__ C,
                    __nv_bfloat16* __restrict__ oqh, __nv_bfloat16* __restrict__ oql,
                    __nv_bfloat16* __restrict__ okh, __nv_bfloat16* __restrict__ okl,
                    __nv_bfloat16* __restrict__ ovh, __nv_bfloat16* __restrict__ ovl,
                    int M, int N, int K)
{
    extern __shared__ __align__(16) char gsm[];
    const uint32_t sb = smem_u32(gsm);

    const int tid  = threadIdx.x;
    const int lane = tid & 31;
    const int wid  = tid >> 5;
    const int brow = blockIdx.y * 128;
    const int bcol = blockIdx.x * 128;

    const int m_base = (wid >> 2) * 64;
    const int n_base = (wid & 3) * 32;

    // per-thread cp.async source/dest precompute: 8 chunks of 16B
    // idx = i*256+tid; arr = idx>>9 (0:Ah 1:Al 2:Bh 3:Bl); j=idx&511; r=j>>2; k8=(j&3)*8
    const __nv_bfloat16* gsrc[8];
    uint32_t sdst[8];
    #pragma unroll
    for (int i = 0; i < 8; i++) {
        int idx = i * 256 + tid;
        int arr = idx >> 9;
        int j   = idx & 511;
        int r   = j >> 2;
        int k8  = (j & 3) << 3;
        const __nv_bfloat16* g =
            (arr == 0) ? &Agh[(size_t)(brow + r) * K + k8] :
            (arr == 1) ? &Agl[(size_t)(brow + r) * K + k8] :
            (arr == 2) ? &Bh [(size_t)(bcol + r) * K + k8] :
                         &Bl [(size_t)(bcol + r) * K + k8];
        gsrc[i] = g;
        sdst[i] = sb + arr * ARR_BYTES + (uint32_t)(r * TSTR + k8) * 2;
    }

    // ldmatrix base offsets (relative; add stage offset at use)
    const int a_r  = lane & 15;
    const int a_k  = (lane >> 4) * 8;
    const uint32_t ah_rel = sb + 0 * ARR_BYTES + ((m_base + a_r) * TSTR + a_k) * 2;
    const uint32_t al_rel = sb + 1 * ARR_BYTES + ((m_base + a_r) * TSTR + a_k) * 2;
    const int b_n  = (lane >> 4) * 8 + (lane & 7);
    const int b_k  = ((lane >> 3) & 1) * 8;
    const uint32_t bh_rel = sb + 2 * ARR_BYTES + ((n_base + b_n) * TSTR + b_k) * 2;
    const uint32_t bl_rel = sb + 3 * ARR_BYTES + ((n_base + b_n) * TSTR + b_k) * 2;

    float acc[4][4][4];
    #pragma unroll
    for (int i = 0; i < 4; i++)
        #pragma unroll
        for (int j = 0; j < 4; j++)
            #pragma unroll
            for (int r = 0; r < 4; r++) acc[i][j][r] = 0.f;

    const int nchunks = K / 32;

    // prefetch stage 0
    #pragma unroll
    for (int i = 0; i < 8; i++) cp_async16(sdst[i], gsrc[i]);
    CP_COMMIT();

    for (int c = 0; c < nchunks; c++) {
        // prefetch next chunk into the other stage
        if (c + 1 < nchunks) {
            const uint32_t so = ((c + 1) & 1) * STG_BYTES;
            const size_t go = (size_t)(c + 1) * 32;
            #pragma unroll
            for (int i = 0; i < 8; i++) cp_async16(sdst[i] + so, gsrc[i] + go);
            CP_COMMIT();
            CP_WAIT(1);
        } else {
            CP_WAIT(0);
        }
        __syncthreads();

        const uint32_t so = (c & 1) * STG_BYTES;
        #pragma unroll
        for (int ks = 0; ks < 32; ks += 16) {
            uint32_t ah[4][4], al[4][4], bh[2][4], bl[2][4];
            #pragma unroll
            for (int mt = 0; mt < 4; mt++) {
                ldsm_x4(ah[mt], ah_rel + so + (mt * 16 * TSTR + ks) * 2);
                ldsm_x4(al[mt], al_rel + so + (mt * 16 * TSTR + ks) * 2);
            }
            #pragma unroll
            for (int p = 0; p < 2; p++) {
                ldsm_x4(bh[p], bh_rel + so + (p * 16 * TSTR + ks) * 2);
                ldsm_x4(bl[p], bl_rel + so + (p * 16 * TSTR + ks) * 2);
            }
            #pragma unroll
            for (int mt = 0; mt < 4; mt++) {
                #pragma unroll
                for (int nt = 0; nt < 4; nt++) {
                    const int p = nt >> 1, h = (nt & 1) * 2;
                    mma16816(acc[mt][nt], ah[mt], bh[p][h], bh[p][h + 1]);
                    mma16816(acc[mt][nt], ah[mt], bl[p][h], bl[p][h + 1]);
                    mma16816(acc[mt][nt], al[mt], bh[p][h], bh[p][h + 1]);
                }
            }
        }
        __syncthreads();
    }

    // --- epilogue ---
    #pragma unroll
    for (int nt = 0; nt < 4; nt++) {
        const int ncol = bcol + n_base + nt * 8 + (lane & 3) * 2;
        float2 bv = *reinterpret_cast<const float2*>(&bias[ncol]);
        if (MODE == 0) {
            #pragma unroll
            for (int mt = 0; mt < 4; mt++) {
                int row0 = brow + m_base + mt * 16 + (lane >> 2);
                float2 v0, v1;
                v0.x = acc[mt][nt][0] + bv.x;  v0.y = acc[mt][nt][1] + bv.y;
                v1.x = acc[mt][nt][2] + bv.x;  v1.y = acc[mt][nt][3] + bv.y;
                *reinterpret_cast<float2*>(&C[(size_t)row0 * N + ncol]) = v0;
                *reinterpret_cast<float2*>(&C[(size_t)(row0 + 8) * N + ncol]) = v1;
            }
        } else {
            const int region = ncol >> 10;
            const int hh = (ncol >> 6) & (HH - 1);
            const int dd = ncol & (HDD - 1);
            __nv_bfloat16* oh = (region == 0) ? oqh : (region == 1) ? okh : ovh;
            __nv_bfloat16* ol = (region == 0) ? oql : (region == 1) ? okl : ovl;
            const float sc = (region == 0) ? QSC : 1.f;
            const size_t colbase = (size_t)hh * (SS * HDD) + dd;
            #pragma unroll
            for (int mt = 0; mt < 4; mt++) {
                int row0 = brow + m_base + mt * 16 + (lane >> 2);
                #pragma unroll
                for (int rr = 0; rr < 2; rr++) {
                    int row = row0 + rr * 8;
                    float v0 = (acc[mt][nt][rr * 2 + 0] + bv.x) * sc;
                    float v1 = (acc[mt][nt][rr * 2 + 1] + bv.y) * sc;
                    __nv_bfloat16 h0 = __float2bfloat16_rn(v0);
                    __nv_bfloat16 h1 = __float2bfloat16_rn(v1);
                    __nv_bfloat16 l0 = __float2bfloat16_rn(v0 - __bfloat162float(h0));
                    __nv_bfloat16 l1 = __float2bfloat16_rn(v1 - __bfloat162float(h1));
                    int bb = row >> 11, ss = row & (SS - 1);
                    size_t off = (size_t)bb * HH * SS * HDD + colbase + (size_t)ss * HDD;
                    *reinterpret_cast<uint32_t*>(&oh[off]) = pack_bf2(h0, h1);
                    *reinterpret_cast<uint32_t*>(&ol[off]) = pack_bf2(l0, l1);
                }
            }
        }
    }
}

// ---------------------------------------------------------------------------
// Tensor-core causal flash attention (as R4, epilogue writes split bf16 y).
// CTA: 64 query rows of one (b,h); 4 warps x 16 rows. 64 keys per iteration.
// ---------------------------------------------------------------------------
#define SM_QH 0
#define SM_QL (64*KSTR*2)
#define SM_KH (2*64*KSTR*2)
#define SM_KL (3*64*KSTR*2)
#define SM_VH (4*64*KSTR*2)
#define SM_VL (5*64*KSTR*2)
#define SM_ATT_TOTAL (6*64*KSTR*2)   // 55296 bytes

__global__ __launch_bounds__(128)
void flash_attn_tc(const __nv_bfloat16* __restrict__ Qh, const __nv_bfloat16* __restrict__ Ql,
                   const __nv_bfloat16* __restrict__ Kh, const __nv_bfloat16* __restrict__ Kl,
                   const __nv_bfloat16* __restrict__ Vh, const __nv_bfloat16* __restrict__ Vl,
                   __nv_bfloat16* __restrict__ yh, __nv_bfloat16* __restrict__ yl)
{
    extern __shared__ __align__(16) char sm[];
    const uint32_t sbase = smem_u32(sm);

    const int tid  = threadIdx.x;
    const int lane = tid & 31;
    const int w    = tid >> 5;
    const int qtile = (gridDim.x - 1) - blockIdx.x;
    const int h = blockIdx.y;
    const int b = blockIdx.z;
    const size_t base = ((size_t)(b * HH + h)) * SS * HDD;

    // ---- load Q tile (once) ----
    {
        const int s0 = qtile * 64;
        #pragma unroll
        for (int i = 0; i < 4; i++) {
            int idx = i * 128 + tid;
            int r  = idx >> 3;
            int c8 = (idx & 7) * 8;
            *reinterpret_cast<uint4*>(sm + SM_QH + (r * KSTR + c8) * 2) =
                *reinterpret_cast<const uint4*>(&Qh[base + (size_t)(s0 + r) * HDD + c8]);
            *reinterpret_cast<uint4*>(sm + SM_QL + (r * KSTR + c8) * 2) =
                *reinterpret_cast<const uint4*>(&Ql[base + (size_t)(s0 + r) * HDD + c8]);
        }
    }
    __syncthreads();

    uint32_t qfh[4][4], qfl[4][4];
    {
        const uint32_t qa = sbase + SM_QH +
            ((w * 16 + (lane & 15)) * KSTR + (lane >> 4) * 8) * 2;
        const uint32_t ql_ = qa + (SM_QL - SM_QH);
        #pragma unroll
        for (int kc = 0; kc < 4; kc++) {
            ldsm_x4(qfh[kc], qa  + kc * 32);
            ldsm_x4(qfl[kc], ql_ + kc * 32);
        }
    }
    __syncthreads();

    const uint32_t ka_h = sbase + SM_KH +
        (((lane >> 4) * 8 + (lane & 7)) * KSTR + ((lane >> 3) & 1) * 8) * 2;
    const uint32_t ka_l = ka_h + (SM_KL - SM_KH);
    const uint32_t va_h = sbase + SM_VH +
        ((((lane >> 3) & 1) * 8 + (lane & 7)) * KSTR + ((lane >> 4) & 1) * 8) * 2;
    const uint32_t va_l = va_h + (SM_VL - SM_VH);

    float o[8][4];
    #pragma unroll
    for (int j = 0; j < 8; j++)
        #pragma unroll
        for (int r = 0; r < 4; r++) o[j][r] = 0.f;
    float m0 = -1e30f, m1 = -1e30f, l0 = 0.f, l1 = 0.f;

    const int row_a0 = qtile * 64 + w * 16 + (lane >> 2);

    for (int kv = 0; kv <= qtile; kv++) {
        const int s0 = kv * 64;
        #pragma unroll
        for (int i = 0; i < 4; i++) {
            int idx = i * 128 + tid;
            int r  = idx >> 3;
            int c8 = (idx & 7) * 8;
            size_t go = base + (size_t)(s0 + r) * HDD + c8;
            uint32_t so = (r * KSTR + c8) * 2;
            *reinterpret_cast<uint4*>(sm + SM_KH + so) =
                *reinterpret_cast<const uint4*>(&Kh[go]);
            *reinterpret_cast<uint4*>(sm + SM_KL + so) =
                *reinterpret_cast<const uint4*>(&Kl[go]);
            *reinterpret_cast<uint4*>(sm + SM_VH + so) =
                *reinterpret_cast<const uint4*>(&Vh[go]);
            *reinterpret_cast<uint4*>(sm + SM_VL + so) =
                *reinterpret_cast<const uint4*>(&Vl[go]);
        }
        __syncthreads();

        float s[8][4];
        #pragma unroll
        for (int j = 0; j < 8; j++)
            #pragma unroll
            for (int r = 0; r < 4; r++) s[j][r] = 0.f;

        #pragma unroll
        for (int kc = 0; kc < 4; kc++) {
            #pragma unroll
            for (int np = 0; np < 4; np++) {
                uint32_t kh4[4], kl4[4];
                ldsm_x4(kh4, ka_h + np * (16 * KSTR * 2) + kc * 32);
                ldsm_x4(kl4, ka_l + np * (16 * KSTR * 2) + kc * 32);
                mma16816(s[2*np],   qfh[kc], kh4[0], kh4[1]);
                mma16816(s[2*np],   qfl[kc], kh4[0], kh4[1]);
                mma16816(s[2*np],   qfh[kc], kl4[0], kl4[1]);
                mma16816(s[2*np+1], qfh[kc], kh4[2], kh4[3]);
                mma16816(s[2*np+1], qfl[kc], kh4[2], kh4[3]);
                mma16816(s[2*np+1], qfh[kc], kl4[2], kl4[3]);
            }
        }

        if (kv == qtile) {
            #pragma unroll
            for (int j = 0; j < 8; j++) {
                int col = kv * 64 + j * 8 + (lane & 3) * 2;
                #pragma unroll
                for (int r = 0; r < 4; r++) {
                    int cc = col + (r & 1);
                    int rw = row_a0 + ((r >= 2) ? 8 : 0);
                    if (cc > rw) s[j][r] = -1e30f;
                }
            }
        }

        float mx0 = -1e30f, mx1 = -1e30f;
        #pragma unroll
        for (int j = 0; j < 8; j++) {
            mx0 = fmaxf(mx0, fmaxf(s[j][0], s[j][1]));
            mx1 = fmaxf(mx1, fmaxf(s[j][2], s[j][3]));
        }
        mx0 = fmaxf(mx0, __shfl_xor_sync(0xffffffffu, mx0, 1));
        mx0 = fmaxf(mx0, __shfl_xor_sync(0xffffffffu, mx0, 2));
        mx1 = fmaxf(mx1, __shfl_xor_sync(0xffffffffu, mx1, 1));
        mx1 = fmaxf(mx1, __shfl_xor_sync(0xffffffffu, mx1, 2));
        float mn0 = fmaxf(m0, mx0), mn1 = fmaxf(m1, mx1);
        float sc0 = ex2f(m0 - mn0), sc1 = ex2f(m1 - mn1);
        m0 = mn0; m1 = mn1;
        l0 *= sc0; l1 *= sc1;
        #pragma unroll
        for (int j = 0; j < 8; j++) {
            o[j][0] *= sc0; o[j][1] *= sc0;
            o[j][2] *= sc1; o[j][3] *= sc1;
        }
        #pragma unroll
        for (int j = 0; j < 8; j++) {
            float p0 = ex2f(s[j][0] - mn0);
            float p1 = ex2f(s[j][1] - mn0);
            float p2 = ex2f(s[j][2] - mn1);
            float p3 = ex2f(s[j][3] - mn1);
            s[j][0] = p0; s[j][1] = p1; s[j][2] = p2; s[j][3] = p3;
            l0 += p0 + p1;
            l1 += p2 + p3;
        }

        #pragma unroll
        for (int kc = 0; kc < 4; kc++) {
            uint32_t aph[4], apl[4];
            #pragma unroll
            for (int t2 = 0; t2 < 2; t2++) {
                int j = 2 * kc + t2;
                __nv_bfloat16 h0 = __float2bfloat16_rn(s[j][0]);
                __nv_bfloat16 h1 = __float2bfloat16_rn(s[j][1]);
                __nv_bfloat16 h2 = __float2bfloat16_rn(s[j][2]);
                __nv_bfloat16 h3 = __float2bfloat16_rn(s[j][3]);
                aph[t2*2 + 0] = pack_bf2(h0, h1);
                aph[t2*2 + 1] = pack_bf2(h2, h3);
                apl[t2*2 + 0] = pack_bf2(
                    __float2bfloat16_rn(s[j][0] - __bfloat162float(h0)),
                    __float2bfloat16_rn(s[j][1] - __bfloat162float(h1)));
                apl[t2*2 + 1] = pack_bf2(
                    __float2bfloat16_rn(s[j][2] - __bfloat162float(h2)),
                    __float2bfloat16_rn(s[j][3] - __bfloat162float(h3)));
            }
            #pragma unroll
            for (int nb = 0; nb < 4; nb++) {
                uint32_t vh4[4], vl4[4];
                ldsm_x4_t(vh4, va_h + kc * (16 * KSTR * 2) + nb * 32);
                ldsm_x4_t(vl4, va_l + kc * (16 * KSTR * 2) + nb * 32);
                mma16816(o[2*nb],   aph, vh4[0], vh4[1]);
                mma16816(o[2*nb],   apl, vh4[0], vh4[1]);
                mma16816(o[2*nb],   aph, vl4[0], vl4[1]);
                mma16816(o[2*nb+1], aph, vh4[2], vh4[3]);
                mma16816(o[2*nb+1], apl, vh4[2], vh4[3]);
                mma16816(o[2*nb+1], aph, vl4[2], vl4[3]);
            }
        }
        __syncthreads();
    }

    l0 += __shfl_xor_sync(0xffffffffu, l0, 1);
    l0 += __shfl_xor_sync(0xffffffffu, l0, 2);
    l1 += __shfl_xor_sync(0xffffffffu, l1, 1);
    l1 += __shfl_xor_sync(0xffffffffu, l1, 2);
    float inv0 = 1.f / l0, inv1 = 1.f / l1;

    // epilogue: write split bf16 y (row-major [8192, 1024])
    size_t tok0 = (size_t)b * SS + row_a0;
    size_t o0 = tok0 * DD + h * HDD + (lane & 3) * 2;
    size_t o1 = o0 + (size_t)8 * DD;
    #pragma unroll
    for (int j = 0; j < 8; j++) {
        float v00 = o[j][0] * inv0, v01 = o[j][1] * inv0;
        float v10 = o[j][2] * inv1, v11 = o[j][3] * inv1;
        __nv_bfloat16 h00 = __float2bfloat16_rn(v00);
        __nv_bfloat16 h01 = __float2bfloat16_rn(v01);
        __nv_bfloat16 h10 = __float2bfloat16_rn(v10);
        __nv_bfloat16 h11 = __float2bfloat16_rn(v11);
        *reinterpret_cast<uint32_t*>(&yh[o0 + j * 8]) = pack_bf2(h00, h01);
        *reinterpret_cast<uint32_t*>(&yl[o0 + j * 8]) = pack_bf2(
            __float2bfloat16_rn(v00 - __bfloat162float(h00)),
            __float2bfloat16_rn(v01 - __bfloat162float(h01)));
        *reinterpret_cast<uint32_t*>(&yh[o1 + j * 8]) = pack_bf2(h10, h11);
        *reinterpret_cast<uint32_t*>(&yl[o1 + j * 8]) = pack_bf2(
            __float2bfloat16_rn(v10 - __bfloat162float(h10)),
            __float2bfloat16_rn(v11 - __bfloat162float(h11)));
    }
}

// ---------------------------------------------------------------------------
// Launch
// ---------------------------------------------------------------------------
extern "C" void kernel_launch(void* const* d_in, const int* in_sizes, int n_in,
                              void* d_out, int out_size)
{
    const float* x      = (const float*)d_in[0];
    const float* W_attn = (const float*)d_in[1];
    const float* b_attn = (const float*)d_in[2];
    const float* W_proj = (const float*)d_in[3];
    const float* b_proj = (const float*)d_in[4];
    float* out = (float*)d_out;

    static __nv_bfloat16 *xh = nullptr, *xl, *yh, *yl;
    static __nv_bfloat16 *wt_hi, *wt_lo, *wpt_hi, *wpt_lo;
    static __nv_bfloat16 *qh, *ql, *kh, *kl, *vh, *vl;
    if (!xh) {   // first (non-captured) correctness call
        cudaGetSymbolAddress((void**)&xh, g_xh);
        cudaGetSymbolAddress((void**)&xl, g_xl);
        cudaGetSymbolAddress((void**)&yh, g_yh);
        cudaGetSymbolAddress((void**)&yl, g_yl);
        cudaGetSymbolAddress((void**)&wt_hi,  g_wt_hi);
        cudaGetSymbolAddress((void**)&wt_lo,  g_wt_lo);
        cudaGetSymbolAddress((void**)&wpt_hi, g_wpt_hi);
        cudaGetSymbolAddress((void**)&wpt_lo, g_wpt_lo);
        cudaGetSymbolAddress((void**)&qh, g_qh);
        cudaGetSymbolAddress((void**)&ql, g_ql);
        cudaGetSymbolAddress((void**)&kh, g_kh);
        cudaGetSymbolAddress((void**)&kl, g_kl);
        cudaGetSymbolAddress((void**)&vh, g_vh);
        cudaGetSymbolAddress((void**)&vl, g_vl);
        cudaFuncSetAttribute(flash_attn_tc,
                             cudaFuncAttributeMaxDynamicSharedMemorySize,
                             SM_ATT_TOTAL);
        cudaFuncSetAttribute(tc_gemm_kernel<0>,
                             cudaFuncAttributeMaxDynamicSharedMemorySize,
                             GEMM_SMEM);
        cudaFuncSetAttribute(tc_gemm_kernel<1>,
                             cudaFuncAttributeMaxDynamicSharedMemorySize,
                             GEMM_SMEM);
    }

    // 0a) split x -> bf16 hi/lo
    split_kernel<<<(MTOK * DD) / (256 * 4), 256>>>(x, xh, xl);
    // 0b) transpose + split weights
    {
        dim3 g1(3 * DD / 32, DD / 32);
        transpose_split_kernel<<<g1, 256>>>(W_attn, wt_hi, wt_lo, DD, 3 * DD);
        dim3 g2(DD / 32, DD / 32);
        transpose_split_kernel<<<g2, 256>>>(W_proj, wpt_hi, wpt_lo, DD, DD);
    }

    // 1) QKV GEMM (pipelined) + fused split epilogue
    {
        dim3 grid(3 * DD / 128, MTOK / 128);
        tc_gemm_kernel<1><<<grid, 256, GEMM_SMEM>>>(
            xh, xl, wt_hi, wt_lo, b_attn, nullptr,
            qh, ql, kh, kl, vh, vl, MTOK, 3 * DD, DD);
    }

    // 2) tensor-core causal flash attention -> split bf16 y
    {
        dim3 grid(SS / 64, HH, BB);
        flash_attn_tc<<<grid, 128, SM_ATT_TOTAL>>>(qh, ql, kh, kl, vh, vl, yh, yl);
    }

    // 3) output projection (pipelined) -> out
    {
        dim3 grid(DD / 128, MTOK / 128);
        tc_gemm_kernel<0><<<grid, 256, GEMM_SMEM>>>(
            yh, yl, wpt_hi, wpt_lo, b_proj, out,
            nullptr, nullptr, nullptr, nullptr, nullptr, nullptr,
            MTOK, DD, DD);
    }
}

// round 6
// speedup vs baseline: 3.4352x; 1.0085x over previous
#include <cuda_runtime.h>
#include <cuda_bf16.h>
#include <cstdint>
#include <cstddef>

// Problem constants
#define BB  4
#define SS  2048
#define DD  1024
#define HH  16
#define HDD 64
#define MTOK (BB*SS)          // 8192 token rows

// q prescale: HD^-0.5 * log2(e)  (softmax done in exp2 domain)
#define QSC 0.18033688011112042f

// Scratch (device globals; no allocations allowed)
__device__ __align__(128) __nv_bfloat16 g_xh[(size_t)MTOK * DD];
__device__ __align__(128) __nv_bfloat16 g_xl[(size_t)MTOK * DD];
__device__ __align__(128) __nv_bfloat16 g_yh[(size_t)MTOK * DD];
__device__ __align__(128) __nv_bfloat16 g_yl[(size_t)MTOK * DD];
__device__ __align__(128) __nv_bfloat16 g_wt_hi [(size_t)3 * DD * DD];
__device__ __align__(128) __nv_bfloat16 g_wt_lo [(size_t)3 * DD * DD];
__device__ __align__(128) __nv_bfloat16 g_wpt_hi[(size_t)DD * DD];
__device__ __align__(128) __nv_bfloat16 g_wpt_lo[(size_t)DD * DD];
#define BHSZ ((size_t)BB * HH * SS * HDD)
__device__ __align__(128) __nv_bfloat16 g_qh[BHSZ], g_ql[BHSZ];
__device__ __align__(128) __nv_bfloat16 g_kh[BHSZ], g_kl[BHSZ];
__device__ __align__(128) __nv_bfloat16 g_vh[BHSZ], g_vl[BHSZ];

// ---------------------------------------------------------------------------
// Warp-MMA + async-copy helpers
// ---------------------------------------------------------------------------
__device__ __forceinline__ uint32_t smem_u32(const void* p) {
    uint32_t a;
    asm("{ .reg .u64 t; cvta.to.shared.u64 t, %1; cvt.u32.u64 %0, t; }"
        : "=r"(a) : "l"(p));
    return a;
}
__device__ __forceinline__ void ldsm_x4(uint32_t* r, uint32_t addr) {
    asm volatile("ldmatrix.sync.aligned.m8n8.x4.shared.b16 {%0,%1,%2,%3}, [%4];"
                 : "=r"(r[0]), "=r"(r[1]), "=r"(r[2]), "=r"(r[3]) : "r"(addr));
}
__device__ __forceinline__ void ldsm_x4_t(uint32_t* r, uint32_t addr) {
    asm volatile("ldmatrix.sync.aligned.m8n8.x4.trans.shared.b16 {%0,%1,%2,%3}, [%4];"
                 : "=r"(r[0]), "=r"(r[1]), "=r"(r[2]), "=r"(r[3]) : "r"(addr));
}
__device__ __forceinline__ void mma16816(float* d, const uint32_t* a,
                                         const uint32_t b0, const uint32_t b1) {
    asm volatile(
        "mma.sync.aligned.m16n8k16.row.col.f32.bf16.bf16.f32 "
        "{%0,%1,%2,%3}, {%4,%5,%6,%7}, {%8,%9}, {%0,%1,%2,%3};"
        : "+f"(d[0]), "+f"(d[1]), "+f"(d[2]), "+f"(d[3])
        : "r"(a[0]), "r"(a[1]), "r"(a[2]), "r"(a[3]), "r"(b0), "r"(b1));
}
__device__ __forceinline__ void cp_async16(uint32_t saddr, const void* g) {
    asm volatile("cp.async.cg.shared.global [%0], [%1], 16;"
                 :: "r"(saddr), "l"(g) : "memory");
}
#define CP_COMMIT() asm volatile("cp.async.commit_group;" ::: "memory")
#define CP_WAIT(n)  asm volatile("cp.async.wait_group %0;" :: "n"(n) : "memory")

__device__ __forceinline__ uint32_t pack_bf2(__nv_bfloat16 a, __nv_bfloat16 b) {
    __nv_bfloat162 t; t.x = a; t.y = b;
    return *reinterpret_cast<uint32_t*>(&t);
}
__device__ __forceinline__ float ex2f(float x) {
    float r;
    asm("ex2.approx.f32 %0, %1;" : "=f"(r) : "f"(x));
    return r;
}

#define TSTR 40   // GEMM tile row stride (elems): 80B rows, conflict-free
#define KSTR 72   // attention tile row stride (elems): 144B rows, conflict-free

// ---------------------------------------------------------------------------
// Elementwise fp32 -> bf16 hi/lo split (for x)
// ---------------------------------------------------------------------------
__global__ __launch_bounds__(256)
void split_kernel(const float* __restrict__ in,
                  __nv_bfloat16* __restrict__ hi,
                  __nv_bfloat16* __restrict__ lo)
{
    size_t i = ((size_t)blockIdx.x * 256 + threadIdx.x) * 4;
    float4 v = *reinterpret_cast<const float4*>(in + i);
    __nv_bfloat16 h0 = __float2bfloat16_rn(v.x);
    __nv_bfloat16 h1 = __float2bfloat16_rn(v.y);
    __nv_bfloat16 h2 = __float2bfloat16_rn(v.z);
    __nv_bfloat16 h3 = __float2bfloat16_rn(v.w);
    uint2 hv, lv;
    hv.x = pack_bf2(h0, h1); hv.y = pack_bf2(h2, h3);
    lv.x = pack_bf2(__float2bfloat16_rn(v.x - __bfloat162float(h0)),
                    __float2bfloat16_rn(v.y - __bfloat162float(h1)));
    lv.y = pack_bf2(__float2bfloat16_rn(v.z - __bfloat162float(h2)),
                    __float2bfloat16_rn(v.w - __bfloat162float(h3)));
    *reinterpret_cast<uint2*>(hi + i) = hv;
    *reinterpret_cast<uint2*>(lo + i) = lv;
}

// ---------------------------------------------------------------------------
// Transpose + bf16 hi/lo split of weights:  W[K,N] fp32 -> Th/Tl[N,K] bf16
// ---------------------------------------------------------------------------
__global__ __launch_bounds__(256)
void transpose_split_kernel(const float* __restrict__ W,
                            __nv_bfloat16* __restrict__ Th,
                            __nv_bfloat16* __restrict__ Tl,
                            int K, int N)
{
    __shared__ float tile[32][33];
    const int n0 = blockIdx.x * 32;
    const int k0 = blockIdx.y * 32;
    const int tx = threadIdx.x & 31;
    const int ty4 = (threadIdx.x >> 5) * 4;

    #pragma unroll
    for (int j = 0; j < 4; j++)
        tile[ty4 + j][tx] = W[(size_t)(k0 + ty4 + j) * N + n0 + tx];
    __syncthreads();
    #pragma unroll
    for (int j = 0; j < 4; j++) {
        float v = tile[tx][ty4 + j];
        __nv_bfloat16 hi = __float2bfloat16_rn(v);
        __nv_bfloat16 lo = __float2bfloat16_rn(v - __bfloat162float(hi));
        size_t o = (size_t)(n0 + ty4 + j) * K + k0 + tx;
        Th[o] = hi;
        Tl[o] = lo;
    }
}

// ---------------------------------------------------------------------------
// cp.async 2-stage, single-barrier tensor-core GEMM (bf16 hi/lo, fp32 accum)
// BM=128, BN=128, BK=32, 256 threads. Pass-major MMA order (RAW dist 16).
// MODE 0: fp32 C.  MODE 1 (QKV): split bf16 q/k/v per-head buffers.
// ---------------------------------------------------------------------------
#define STG_BYTES (4 * 128 * TSTR * 2)    // 40960 per stage
#define ARR_BYTES (128 * TSTR * 2)        // 10240 per array
#define GEMM_SMEM (2 * STG_BYTES)         // 81920

template <int MODE>
__global__ __launch_bounds__(256, 2)
void tc_gemm_kernel(const __nv_bfloat16* __restrict__ Agh,
                    const __nv_bfloat16* __restrict__ Agl,
                    const __nv_bfloat16* __restrict__ Bh,
                    const __nv_bfloat16* __restrict__ Bl,
                    const float* __restrict__ bias,
                    float* __restrict__ C,
                    __nv_bfloat16* __restrict__ oqh, __nv_bfloat16* __restrict__ oql,
                    __nv_bfloat16* __restrict__ okh, __nv_bfloat16* __restrict__ okl,
                    __nv_bfloat16* __restrict__ ovh, __nv_bfloat16* __restrict__ ovl,
                    int M, int N, int K)
{
    extern __shared__ __align__(16) char gsm[];
    const uint32_t sb = smem_u32(gsm);

    const int tid  = threadIdx.x;
    const int lane = tid & 31;
    const int wid  = tid >> 5;
    const int brow = blockIdx.y * 128;
    const int bcol = blockIdx.x * 128;

    const int m_base = (wid >> 2) * 64;
    const int n_base = (wid & 3) * 32;

    // per-thread cp.async src/dst: 8 chunks of 16B
    const __nv_bfloat16* gsrc[8];
    uint32_t sdst[8];
    #pragma unroll
    for (int i = 0; i < 8; i++) {
        int idx = i * 256 + tid;
        int arr = idx >> 9;
        int j   = idx & 511;
        int r   = j >> 2;
        int k8  = (j & 3) << 3;
        const __nv_bfloat16* g =
            (arr == 0) ? &Agh[(size_t)(brow + r) * K + k8] :
            (arr == 1) ? &Agl[(size_t)(brow + r) * K + k8] :
            (arr == 2) ? &Bh [(size_t)(bcol + r) * K + k8] :
                         &Bl [(size_t)(bcol + r) * K + k8];
        gsrc[i] = g;
        sdst[i] = sb + arr * ARR_BYTES + (uint32_t)(r * TSTR + k8) * 2;
    }

    const int a_r  = lane & 15;
    const int a_k  = (lane >> 4) * 8;
    const uint32_t ah_rel = sb + 0 * ARR_BYTES + ((m_base + a_r) * TSTR + a_k) * 2;
    const uint32_t al_rel = sb + 1 * ARR_BYTES + ((m_base + a_r) * TSTR + a_k) * 2;
    const int b_n  = (lane >> 4) * 8 + (lane & 7);
    const int b_k  = ((lane >> 3) & 1) * 8;
    const uint32_t bh_rel = sb + 2 * ARR_BYTES + ((n_base + b_n) * TSTR + b_k) * 2;
    const uint32_t bl_rel = sb + 3 * ARR_BYTES + ((n_base + b_n) * TSTR + b_k) * 2;

    float acc[4][4][4];
    #pragma unroll
    for (int i = 0; i < 4; i++)
        #pragma unroll
        for (int j = 0; j < 4; j++)
            #pragma unroll
            for (int r = 0; r < 4; r++) acc[i][j][r] = 0.f;

    const int nchunks = K / 32;

    // prologue: stage 0
    #pragma unroll
    for (int i = 0; i < 8; i++) cp_async16(sdst[i], gsrc[i]);
    CP_COMMIT();

    for (int c = 0; c < nchunks; c++) {
        CP_WAIT(0);
        __syncthreads();   // stage c visible; all warps done with stage (c+1)&1

        if (c + 1 < nchunks) {
            const uint32_t so = ((c + 1) & 1) * STG_BYTES;
            const size_t go = (size_t)(c + 1) * 32;
            #pragma unroll
            for (int i = 0; i < 8; i++) cp_async16(sdst[i] + so, gsrc[i] + go);
            CP_COMMIT();
        }

        const uint32_t so = (c & 1) * STG_BYTES;
        #pragma unroll
        for (int ks = 0; ks < 32; ks += 16) {
            uint32_t ah[4][4], al[4][4], bh[2][4], bl[2][4];
            #pragma unroll
            for (int mt = 0; mt < 4; mt++) {
                ldsm_x4(ah[mt], ah_rel + so + (mt * 16 * TSTR + ks) * 2);
                ldsm_x4(al[mt], al_rel + so + (mt * 16 * TSTR + ks) * 2);
            }
            #pragma unroll
            for (int p = 0; p < 2; p++) {
                ldsm_x4(bh[p], bh_rel + so + (p * 16 * TSTR + ks) * 2);
                ldsm_x4(bl[p], bl_rel + so + (p * 16 * TSTR + ks) * 2);
            }
            // pass-major ordering: accumulator RAW distance = 16 MMAs
            #pragma unroll
            for (int mt = 0; mt < 4; mt++)
                #pragma unroll
                for (int nt = 0; nt < 4; nt++) {
                    const int p = nt >> 1, h = (nt & 1) * 2;
                    mma16816(acc[mt][nt], ah[mt], bh[p][h], bh[p][h + 1]);
                }
            #pragma unroll
            for (int mt = 0; mt < 4; mt++)
                #pragma unroll
                for (int nt = 0; nt < 4; nt++) {
                    const int p = nt >> 1, h = (nt & 1) * 2;
                    mma16816(acc[mt][nt], ah[mt], bl[p][h], bl[p][h + 1]);
                }
            #pragma unroll
            for (int mt = 0; mt < 4; mt++)
                #pragma unroll
                for (int nt = 0; nt < 4; nt++) {
                    const int p = nt >> 1, h = (nt & 1) * 2;
                    mma16816(acc[mt][nt], al[mt], bh[p][h], bh[p][h + 1]);
                }
        }
    }

    // --- epilogue ---
    #pragma unroll
    for (int nt = 0; nt < 4; nt++) {
        const int ncol = bcol + n_base + nt * 8 + (lane & 3) * 2;
        float2 bv = *reinterpret_cast<const float2*>(&bias[ncol]);
        if (MODE == 0) {
            #pragma unroll
            for (int mt = 0; mt < 4; mt++) {
                int row0 = brow + m_base + mt * 16 + (lane >> 2);
                float2 v0, v1;
                v0.x = acc[mt][nt][0] + bv.x;  v0.y = acc[mt][nt][1] + bv.y;
                v1.x = acc[mt][nt][2] + bv.x;  v1.y = acc[mt][nt][3] + bv.y;
                *reinterpret_cast<float2*>(&C[(size_t)row0 * N + ncol]) = v0;
                *reinterpret_cast<float2*>(&C[(size_t)(row0 + 8) * N + ncol]) = v1;
            }
        } else {
            const int region = ncol >> 10;
            const int hh = (ncol >> 6) & (HH - 1);
            const int dd = ncol & (HDD - 1);
            __nv_bfloat16* oh = (region == 0) ? oqh : (region == 1) ? okh : ovh;
            __nv_bfloat16* ol = (region == 0) ? oql : (region == 1) ? okl : ovl;
            const float sc = (region == 0) ? QSC : 1.f;
            const size_t colbase = (size_t)hh * (SS * HDD) + dd;
            #pragma unroll
            for (int mt = 0; mt < 4; mt++) {
                int row0 = brow + m_base + mt * 16 + (lane >> 2);
                #pragma unroll
                for (int rr = 0; rr < 2; rr++) {
                    int row = row0 + rr * 8;
                    float v0 = (acc[mt][nt][rr * 2 + 0] + bv.x) * sc;
                    float v1 = (acc[mt][nt][rr * 2 + 1] + bv.y) * sc;
                    __nv_bfloat16 h0 = __float2bfloat16_rn(v0);
                    __nv_bfloat16 h1 = __float2bfloat16_rn(v1);
                    __nv_bfloat16 l0 = __float2bfloat16_rn(v0 - __bfloat162float(h0));
                    __nv_bfloat16 l1 = __float2bfloat16_rn(v1 - __bfloat162float(h1));
                    int bb = row >> 11, ss = row & (SS - 1);
                    size_t off = (size_t)bb * HH * SS * HDD + colbase + (size_t)ss * HDD;
                    *reinterpret_cast<uint32_t*>(&oh[off]) = pack_bf2(h0, h1);
                    *reinterpret_cast<uint32_t*>(&ol[off]) = pack_bf2(l0, l1);
                }
            }
        }
    }
}

// ---------------------------------------------------------------------------
// Tensor-core causal flash attention with cp.async 2-stage K/V ring,
// single barrier per KV tile, interleaved MMA ordering.
// CTA: 64 query rows of one (b,h); 4 warps x 16 rows. 64 keys per iteration.
// ---------------------------------------------------------------------------
#define FS_STG  36864                  // 4 arrays x 64 x KSTR x 2B
#define FS_KH   0
#define FS_KL   9216
#define FS_VH   18432
#define FS_VL   27648
#define FS_TOTAL (2 * FS_STG)          // 73728 bytes

__global__ __launch_bounds__(128, 3)
void flash_attn_tc(const __nv_bfloat16* __restrict__ Qh, const __nv_bfloat16* __restrict__ Ql,
                   const __nv_bfloat16* __restrict__ Kh, const __nv_bfloat16* __restrict__ Kl,
                   const __nv_bfloat16* __restrict__ Vh, const __nv_bfloat16* __restrict__ Vl,
                   __nv_bfloat16* __restrict__ yh, __nv_bfloat16* __restrict__ yl)
{
    extern __shared__ __align__(16) char sm[];
    const uint32_t sbase = smem_u32(sm);

    const int tid  = threadIdx.x;
    const int lane = tid & 31;
    const int w    = tid >> 5;
    const int qtile = (gridDim.x - 1) - blockIdx.x;   // long tiles first
    const int h = blockIdx.y;
    const int b = blockIdx.z;
    const size_t base = ((size_t)(b * HH + h)) * SS * HDD;

    // per-thread K/V cp.async chunk offsets (4 x 16B per 64x64 array)
    int goff[4]; uint32_t soff[4];
    #pragma unroll
    for (int ii = 0; ii < 4; ii++) {
        int j  = ii * 128 + tid;     // 0..511
        int r  = j >> 3;
        int c8 = (j & 7) * 8;
        goff[ii] = r * HDD + c8;
        soff[ii] = (uint32_t)(r * KSTR + c8) * 2;
    }

    // ---- load Q (into stage-0 region), build frags ----
    {
        const int s0 = qtile * 64;
        #pragma unroll
        for (int i = 0; i < 4; i++) {
            int idx = i * 128 + tid;
            int r  = idx >> 3;
            int c8 = (idx & 7) * 8;
            uint32_t so = (uint32_t)(r * KSTR + c8) * 2;
            *reinterpret_cast<uint4*>(sm + so) =
                *reinterpret_cast<const uint4*>(&Qh[base + (size_t)(s0 + r) * HDD + c8]);
            *reinterpret_cast<uint4*>(sm + 9216 + so) =
                *reinterpret_cast<const uint4*>(&Ql[base + (size_t)(s0 + r) * HDD + c8]);
        }
    }
    __syncthreads();

    uint32_t qfh[4][4], qfl[4][4];
    {
        const uint32_t qa = sbase +
            ((w * 16 + (lane & 15)) * KSTR + (lane >> 4) * 8) * 2;
        #pragma unroll
        for (int kc = 0; kc < 4; kc++) {
            ldsm_x4(qfh[kc], qa + kc * 32);
            ldsm_x4(qfl[kc], qa + 9216 + kc * 32);
        }
    }
    __syncthreads();   // Q smem dead; stage 0 reusable

    // ldsm per-thread relative offsets (within a stage)
    const uint32_t ka_rel = (((lane >> 4) * 8 + (lane & 7)) * KSTR +
                             ((lane >> 3) & 1) * 8) * 2;
    const uint32_t va_rel = ((((lane >> 3) & 1) * 8 + (lane & 7)) * KSTR +
                             ((lane >> 4) & 1) * 8) * 2;

    float o[8][4];
    #pragma unroll
    for (int j = 0; j < 8; j++)
        #pragma unroll
        for (int r = 0; r < 4; r++) o[j][r] = 0.f;
    float m0 = -1e30f, m1 = -1e30f, l0 = 0.f, l1 = 0.f;

    const int row_a0 = qtile * 64 + w * 16 + (lane >> 2);

    // prologue: issue KV tile 0 into stage 0
    {
        const uint32_t sa = sbase;
        #pragma unroll
        for (int ii = 0; ii < 4; ii++) {
            cp_async16(sa + FS_KH + soff[ii], Kh + base + goff[ii]);
            cp_async16(sa + FS_KL + soff[ii], Kl + base + goff[ii]);
            cp_async16(sa + FS_VH + soff[ii], Vh + base + goff[ii]);
            cp_async16(sa + FS_VL + soff[ii], Vl + base + goff[ii]);
        }
        CP_COMMIT();
    }

    for (int kv = 0; kv <= qtile; kv++) {
        CP_WAIT(0);
        __syncthreads();   // stage kv visible; all done with stage (kv+1)&1

        if (kv < qtile) {
            const uint32_t sa = sbase + ((kv + 1) & 1) * FS_STG;
            const size_t gb = base + (size_t)(kv + 1) * 64 * HDD;
            #pragma unroll
            for (int ii = 0; ii < 4; ii++) {
                cp_async16(sa + FS_KH + soff[ii], Kh + gb + goff[ii]);
                cp_async16(sa + FS_KL + soff[ii], Kl + gb + goff[ii]);
                cp_async16(sa + FS_VH + soff[ii], Vh + gb + goff[ii]);
                cp_async16(sa + FS_VL + soff[ii], Vl + gb + goff[ii]);
            }
            CP_COMMIT();
        }

        const uint32_t sa = sbase + (kv & 1) * FS_STG;
        const uint32_t ka_h = sa + FS_KH + ka_rel;
        const uint32_t ka_l = sa + FS_KL + ka_rel;
        const uint32_t va_h = sa + FS_VH + va_rel;
        const uint32_t va_l = sa + FS_VL + va_rel;

        // ---- S = Q K^T ----
        float s[8][4];
        #pragma unroll
        for (int j = 0; j < 8; j++)
            #pragma unroll
            for (int r = 0; r < 4; r++) s[j][r] = 0.f;

        #pragma unroll
        for (int kc = 0; kc < 4; kc++) {
            #pragma unroll
            for (int np = 0; np < 4; np++) {
                uint32_t kh4[4], kl4[4];
                ldsm_x4(kh4, ka_h + np * (16 * KSTR * 2) + kc * 32);
                ldsm_x4(kl4, ka_l + np * (16 * KSTR * 2) + kc * 32);
                // interleaved: alternate between the two acc tiles
                mma16816(s[2*np],   qfh[kc], kh4[0], kh4[1]);
                mma16816(s[2*np+1], qfh[kc], kh4[2], kh4[3]);
                mma16816(s[2*np],   qfl[kc], kh4[0], kh4[1]);
                mma16816(s[2*np+1], qfl[kc], kh4[2], kh4[3]);
                mma16816(s[2*np],   qfh[kc], kl4[0], kl4[1]);
                mma16816(s[2*np+1], qfh[kc], kl4[2], kl4[3]);
            }
        }

        // ---- causal mask (diagonal tile only) ----
        if (kv == qtile) {
            #pragma unroll
            for (int j = 0; j < 8; j++) {
                int col = kv * 64 + j * 8 + (lane & 3) * 2;
                #pragma unroll
                for (int r = 0; r < 4; r++) {
                    int cc = col + (r & 1);
                    int rw = row_a0 + ((r >= 2) ? 8 : 0);
                    if (cc > rw) s[j][r] = -1e30f;
                }
            }
        }

        // ---- online softmax ----
        float mx0 = -1e30f, mx1 = -1e30f;
        #pragma unroll
        for (int j = 0; j < 8; j++) {
            mx0 = fmaxf(mx0, fmaxf(s[j][0], s[j][1]));
            mx1 = fmaxf(mx1, fmaxf(s[j][2], s[j][3]));
        }
        mx0 = fmaxf(mx0, __shfl_xor_sync(0xffffffffu, mx0, 1));
        mx0 = fmaxf(mx0, __shfl_xor_sync(0xffffffffu, mx0, 2));
        mx1 = fmaxf(mx1, __shfl_xor_sync(0xffffffffu, mx1, 1));
        mx1 = fmaxf(mx1, __shfl_xor_sync(0xffffffffu, mx1, 2));
        float mn0 = fmaxf(m0, mx0), mn1 = fmaxf(m1, mx1);
        float sc0 = ex2f(m0 - mn0), sc1 = ex2f(m1 - mn1);
        m0 = mn0; m1 = mn1;
        l0 *= sc0; l1 *= sc1;
        #pragma unroll
        for (int j = 0; j < 8; j++) {
            o[j][0] *= sc0; o[j][1] *= sc0;
            o[j][2] *= sc1; o[j][3] *= sc1;
        }
        #pragma unroll
        for (int j = 0; j < 8; j++) {
            float p0 = ex2f(s[j][0] - mn0);
            float p1 = ex2f(s[j][1] - mn0);
            float p2 = ex2f(s[j][2] - mn1);
            float p3 = ex2f(s[j][3] - mn1);
            s[j][0] = p0; s[j][1] = p1; s[j][2] = p2; s[j][3] = p3;
            l0 += p0 + p1;
            l1 += p2 + p3;
        }

        // ---- O += P V ----
        #pragma unroll
        for (int kc = 0; kc < 4; kc++) {
            uint32_t aph[4], apl[4];
            #pragma unroll
            for (int t2 = 0; t2 < 2; t2++) {
                int j = 2 * kc + t2;
                __nv_bfloat16 h0 = __float2bfloat16_rn(s[j][0]);
                __nv_bfloat16 h1 = __float2bfloat16_rn(s[j][1]);
                __nv_bfloat16 h2 = __float2bfloat16_rn(s[j][2]);
                __nv_bfloat16 h3 = __float2bfloat16_rn(s[j][3]);
                aph[t2*2 + 0] = pack_bf2(h0, h1);
                aph[t2*2 + 1] = pack_bf2(h2, h3);
                apl[t2*2 + 0] = pack_bf2(
                    __float2bfloat16_rn(s[j][0] - __bfloat162float(h0)),
                    __float2bfloat16_rn(s[j][1] - __bfloat162float(h1)));
                apl[t2*2 + 1] = pack_bf2(
                    __float2bfloat16_rn(s[j][2] - __bfloat162float(h2)),
                    __float2bfloat16_rn(s[j][3] - __bfloat162float(h3)));
            }
            #pragma unroll
            for (int nb = 0; nb < 4; nb++) {
                uint32_t vh4[4], vl4[4];
                ldsm_x4_t(vh4, va_h + kc * (16 * KSTR * 2) + nb * 32);
                ldsm_x4_t(vl4, va_l + kc * (16 * KSTR * 2) + nb * 32);
                mma16816(o[2*nb],   aph, vh4[0], vh4[1]);
                mma16816(o[2*nb+1], aph, vh4[2], vh4[3]);
                mma16816(o[2*nb],   apl, vh4[0], vh4[1]);
                mma16816(o[2*nb+1], apl, vh4[2], vh4[3]);
                mma16816(o[2*nb],   aph, vl4[0], vl4[1]);
                mma16816(o[2*nb+1], aph, vl4[2], vl4[3]);
            }
        }
    }

    l0 += __shfl_xor_sync(0xffffffffu, l0, 1);
    l0 += __shfl_xor_sync(0xffffffffu, l0, 2);
    l1 += __shfl_xor_sync(0xffffffffu, l1, 1);
    l1 += __shfl_xor_sync(0xffffffffu, l1, 2);
    float inv0 = 1.f / l0, inv1 = 1.f / l1;

    // epilogue: write split bf16 y (row-major [8192, 1024])
    size_t tok0 = (size_t)b * SS + row_a0;
    size_t o0 = tok0 * DD + h * HDD + (lane & 3) * 2;
    size_t o1 = o0 + (size_t)8 * DD;
    #pragma unroll
    for (int j = 0; j < 8; j++) {
        float v00 = o[j][0] * inv0, v01 = o[j][1] * inv0;
        float v10 = o[j][2] * inv1, v11 = o[j][3] * inv1;
        __nv_bfloat16 h00 = __float2bfloat16_rn(v00);
        __nv_bfloat16 h01 = __float2bfloat16_rn(v01);
        __nv_bfloat16 h10 = __float2bfloat16_rn(v10);
        __nv_bfloat16 h11 = __float2bfloat16_rn(v11);
        *reinterpret_cast<uint32_t*>(&yh[o0 + j * 8]) = pack_bf2(h00, h01);
        *reinterpret_cast<uint32_t*>(&yl[o0 + j * 8]) = pack_bf2(
            __float2bfloat16_rn(v00 - __bfloat162float(h00)),
            __float2bfloat16_rn(v01 - __bfloat162float(h01)));
        *reinterpret_cast<uint32_t*>(&yh[o1 + j * 8]) = pack_bf2(h10, h11);
        *reinterpret_cast<uint32_t*>(&yl[o1 + j * 8]) = pack_bf2(
            __float2bfloat16_rn(v10 - __bfloat162float(h10)),
            __float2bfloat16_rn(v11 - __bfloat162float(h11)));
    }
}

// ---------------------------------------------------------------------------
// Launch
// ---------------------------------------------------------------------------
extern "C" void kernel_launch(void* const* d_in, const int* in_sizes, int n_in,
                              void* d_out, int out_size)
{
    const float* x      = (const float*)d_in[0];
    const float* W_attn = (const float*)d_in[1];
    const float* b_attn = (const float*)d_in[2];
    const float* W_proj = (const float*)d_in[3];
    const float* b_proj = (const float*)d_in[4];
    float* out = (float*)d_out;

    static __nv_bfloat16 *xh = nullptr, *xl, *yh, *yl;
    static __nv_bfloat16 *wt_hi, *wt_lo, *wpt_hi, *wpt_lo;
    static __nv_bfloat16 *qh, *ql, *kh, *kl, *vh, *vl;
    if (!xh) {   // first (non-captured) correctness call
        cudaGetSymbolAddress((void**)&xh, g_xh);
        cudaGetSymbolAddress((void**)&xl, g_xl);
        cudaGetSymbolAddress((void**)&yh, g_yh);
        cudaGetSymbolAddress((void**)&yl, g_yl);
        cudaGetSymbolAddress((void**)&wt_hi,  g_wt_hi);
        cudaGetSymbolAddress((void**)&wt_lo,  g_wt_lo);
        cudaGetSymbolAddress((void**)&wpt_hi, g_wpt_hi);
        cudaGetSymbolAddress((void**)&wpt_lo, g_wpt_lo);
        cudaGetSymbolAddress((void**)&qh, g_qh);
        cudaGetSymbolAddress((void**)&ql, g_ql);
        cudaGetSymbolAddress((void**)&kh, g_kh);
        cudaGetSymbolAddress((void**)&kl, g_kl);
        cudaGetSymbolAddress((void**)&vh, g_vh);
        cudaGetSymbolAddress((void**)&vl, g_vl);
        cudaFuncSetAttribute(flash_attn_tc,
                             cudaFuncAttributeMaxDynamicSharedMemorySize,
                             FS_TOTAL);
        cudaFuncSetAttribute(tc_gemm_kernel<0>,
                             cudaFuncAttributeMaxDynamicSharedMemorySize,
                             GEMM_SMEM);
        cudaFuncSetAttribute(tc_gemm_kernel<1>,
                             cudaFuncAttributeMaxDynamicSharedMemorySize,
                             GEMM_SMEM);
    }

    // 0a) split x -> bf16 hi/lo
    split_kernel<<<(MTOK * DD) / (256 * 4), 256>>>(x, xh, xl);
    // 0b) transpose + split weights
    {
        dim3 g1(3 * DD / 32, DD / 32);
        transpose_split_kernel<<<g1, 256>>>(W_attn, wt_hi, wt_lo, DD, 3 * DD);
        dim3 g2(DD / 32, DD / 32);
        transpose_split_kernel<<<g2, 256>>>(W_proj, wpt_hi, wpt_lo, DD, DD);
    }

    // 1) QKV GEMM (pipelined) + fused split epilogue
    {
        dim3 grid(3 * DD / 128, MTOK / 128);
        tc_gemm_kernel<1><<<grid, 256, GEMM_SMEM>>>(
            xh, xl, wt_hi, wt_lo, b_attn, nullptr,
            qh, ql, kh, kl, vh, vl, MTOK, 3 * DD, DD);
    }

    // 2) tensor-core causal flash attention -> split bf16 y
    {
        dim3 grid(SS / 64, HH, BB);
        flash_attn_tc<<<grid, 128, FS_TOTAL>>>(qh, ql, kh, kl, vh, vl, yh, yl);
    }

    // 3) output projection (pipelined) -> out
    {
        dim3 grid(DD / 128, MTOK / 128);
        tc_gemm_kernel<0><<<grid, 256, GEMM_SMEM>>>(
            yh, yl, wpt_hi, wpt_lo, b_proj, out,
            nullptr, nullptr, nullptr, nullptr, nullptr, nullptr,
            MTOK, DD, DD);
    }
}